// round 2
// baseline (speedup 1.0000x reference)
#include <cuda_runtime.h>
#include <cstdint>

// Problem constants
#define NB   2
#define CCH  512
#define MM   8
#define FLV  4
#define SSQ  13294   // 10000 + 2500 + 625 + 169

__constant__ int c_lvl_off[4] = {0, 10000, 12500, 13125};
__constant__ int c_lvl_w[4]   = {100, 50, 25, 13};   // H == W per level

// Scratch (allocation-free rule => __device__ globals)
__device__ float g_value[(size_t)NB * SSQ * CCH];  // (n, s, c)  c-contiguous
__device__ float g_offw [(size_t)NB * SSQ * 96];   // (n, s, r)  r: 0..63 = off rows, 64..95 = w rows
__device__ float g_samp [(size_t)NB * SSQ * CCH];  // (n, s, c)

// ---------------------------------------------------------------------------
// GEMM 1: value_t[n, s, o] = sum_c Wv[o,c] * x[n,c,s] + bv[o]
// Tile 128(s) x 128(o), K-chunk 8.
// NOTE: x rows have stride SSQ=13294 (== 2 mod 4) -> only 8B alignment
// guaranteed on s-contiguous loads: use float2, never float4.
// ---------------------------------------------------------------------------
__global__ void __launch_bounds__(256) k_gemm_value(
    const float* __restrict__ x, const float* __restrict__ Wv,
    const float* __restrict__ bv)
{
    __shared__ float As[8][132];  // [k][s]
    __shared__ float Bs[8][132];  // [k][o]
    const int n  = blockIdx.z;
    const int s0 = blockIdx.x * 128;
    const int o0 = blockIdx.y * 128;
    const int t  = threadIdx.x;
    const int tx = t & 15;
    const int ty = t >> 4;

    const float* xn = x + (size_t)n * CCH * SSQ;

    float acc[8][8];
#pragma unroll
    for (int i = 0; i < 8; i++)
#pragma unroll
        for (int j = 0; j < 8; j++) acc[i][j] = 0.f;

    const int lk  = t >> 5;          // 0..7
    const int ls4 = (t & 31) << 2;   // 0..124
    const int lo  = t >> 1;          // 0..127
    const int lk4 = (t & 1) << 2;    // 0 or 4

    for (int c0 = 0; c0 < CCH; c0 += 8) {
        const float* srcA = xn + (size_t)(c0 + lk) * SSQ + s0 + ls4;
        float4 av;
        if (s0 + ls4 + 3 < SSQ) {
            float2 a0 = *(const float2*)(srcA);      // 8B aligned (even offset)
            float2 a1 = *(const float2*)(srcA + 2);
            av = make_float4(a0.x, a0.y, a1.x, a1.y);
        } else {
            av.x = (s0 + ls4 + 0 < SSQ) ? srcA[0] : 0.f;
            av.y = (s0 + ls4 + 1 < SSQ) ? srcA[1] : 0.f;
            av.z = (s0 + ls4 + 2 < SSQ) ? srcA[2] : 0.f;
            av.w = (s0 + ls4 + 3 < SSQ) ? srcA[3] : 0.f;
        }
        *(float4*)&As[lk][ls4] = av;

        float4 wv4 = *(const float4*)(Wv + (size_t)(o0 + lo) * CCH + c0 + lk4);
        Bs[lk4 + 0][lo] = wv4.x;
        Bs[lk4 + 1][lo] = wv4.y;
        Bs[lk4 + 2][lo] = wv4.z;
        Bs[lk4 + 3][lo] = wv4.w;
        __syncthreads();

#pragma unroll
        for (int k = 0; k < 8; k++) {
            float a[8], b[8];
            *(float4*)&a[0] = *(const float4*)&As[k][ty * 8];
            *(float4*)&a[4] = *(const float4*)&As[k][ty * 8 + 4];
            *(float4*)&b[0] = *(const float4*)&Bs[k][tx * 4];
            *(float4*)&b[4] = *(const float4*)&Bs[k][64 + tx * 4];
#pragma unroll
            for (int i = 0; i < 8; i++)
#pragma unroll
                for (int j = 0; j < 8; j++)
                    acc[i][j] = fmaf(a[i], b[j], acc[i][j]);
        }
        __syncthreads();
    }

    float bias[8];
#pragma unroll
    for (int j = 0; j < 4; j++) {
        bias[j]     = bv[o0 + tx * 4 + j];
        bias[4 + j] = bv[o0 + 64 + tx * 4 + j];
    }
#pragma unroll
    for (int i = 0; i < 8; i++) {
        int s = s0 + ty * 8 + i;
        if (s < SSQ) {
            float* dst = g_value + ((size_t)n * SSQ + s) * CCH + o0;
            float4 v0 = make_float4(acc[i][0] + bias[0], acc[i][1] + bias[1],
                                    acc[i][2] + bias[2], acc[i][3] + bias[3]);
            float4 v1 = make_float4(acc[i][4] + bias[4], acc[i][5] + bias[5],
                                    acc[i][6] + bias[6], acc[i][7] + bias[7]);
            *(float4*)(dst + tx * 4)      = v0;
            *(float4*)(dst + 64 + tx * 4) = v1;
        }
    }
}

// ---------------------------------------------------------------------------
// GEMM 2: offw[n, s, r] = sum_c W[r,c] * (x+pos)[n,c,s] + b[r]
//   r in [0,64): Wloc/bloc ; r in [64,96): Ww/bw
// ---------------------------------------------------------------------------
__global__ void __launch_bounds__(256) k_gemm_locw(
    const float* __restrict__ x, const float* __restrict__ pos,
    const float* __restrict__ Wloc, const float* __restrict__ bloc,
    const float* __restrict__ Ww,   const float* __restrict__ bw)
{
    __shared__ float As[8][132];
    __shared__ float Bs[8][100];
    const int n  = blockIdx.z;
    const int s0 = blockIdx.x * 128;
    const int t  = threadIdx.x;
    const int tx = t & 15;
    const int ty = t >> 4;

    const float* xn = x   + (size_t)n * CCH * SSQ;
    const float* pn = pos + (size_t)n * CCH * SSQ;

    float acc[6][8];
#pragma unroll
    for (int i = 0; i < 6; i++)
#pragma unroll
        for (int j = 0; j < 8; j++) acc[i][j] = 0.f;

    const int lk  = t >> 5;
    const int ls4 = (t & 31) << 2;
    const int lr  = t >> 1;          // 0..127 (valid < 96)
    const int lk4 = (t & 1) << 2;

    for (int c0 = 0; c0 < CCH; c0 += 8) {
        size_t off = (size_t)(c0 + lk) * SSQ + s0 + ls4;
        float4 av;
        if (s0 + ls4 + 3 < SSQ) {
            float2 xa0 = *(const float2*)(xn + off);
            float2 xa1 = *(const float2*)(xn + off + 2);
            float2 pa0 = *(const float2*)(pn + off);
            float2 pa1 = *(const float2*)(pn + off + 2);
            av = make_float4(xa0.x + pa0.x, xa0.y + pa0.y,
                             xa1.x + pa1.x, xa1.y + pa1.y);
        } else {
            av.x = (s0 + ls4 + 0 < SSQ) ? (xn[off + 0] + pn[off + 0]) : 0.f;
            av.y = (s0 + ls4 + 1 < SSQ) ? (xn[off + 1] + pn[off + 1]) : 0.f;
            av.z = (s0 + ls4 + 2 < SSQ) ? (xn[off + 2] + pn[off + 2]) : 0.f;
            av.w = (s0 + ls4 + 3 < SSQ) ? (xn[off + 3] + pn[off + 3]) : 0.f;
        }
        *(float4*)&As[lk][ls4] = av;

        if (t < 192) {
            const float* wp = (lr < 64) ? (Wloc + (size_t)lr * CCH)
                                        : (Ww + (size_t)(lr - 64) * CCH);
            float4 w4 = *(const float4*)(wp + c0 + lk4);
            Bs[lk4 + 0][lr] = w4.x;
            Bs[lk4 + 1][lr] = w4.y;
            Bs[lk4 + 2][lr] = w4.z;
            Bs[lk4 + 3][lr] = w4.w;
        }
        __syncthreads();

#pragma unroll
        for (int k = 0; k < 8; k++) {
            float a[8];
            *(float4*)&a[0] = *(const float4*)&As[k][tx * 4];
            *(float4*)&a[4] = *(const float4*)&As[k][64 + tx * 4];
            float b[6];
#pragma unroll
            for (int i = 0; i < 6; i++) b[i] = Bs[k][ty * 6 + i];
#pragma unroll
            for (int i = 0; i < 6; i++)
#pragma unroll
                for (int j = 0; j < 8; j++)
                    acc[i][j] = fmaf(b[i], a[j], acc[i][j]);
        }
        __syncthreads();
    }

#pragma unroll
    for (int i = 0; i < 6; i++) {
        int r = ty * 6 + i;
        float bb = (r < 64) ? bloc[r] : bw[r - 64];
#pragma unroll
        for (int j = 0; j < 8; j++) {
            int s = s0 + ((j < 4) ? (tx * 4 + j) : (64 + tx * 4 + (j - 4)));
            if (s < SSQ)
                g_offw[((size_t)n * SSQ + s) * 96 + r] = acc[i][j] + bb;
        }
    }
}

// ---------------------------------------------------------------------------
// Sampling: one warp per (n, q, m). 64 channels per head -> lane and lane+32.
// samp[n, q, m*64+cc] = sum_f softmax_w[f] * bilinear(value level f, head m)
// ---------------------------------------------------------------------------
__global__ void __launch_bounds__(256) k_sample(
    const float* __restrict__ valid_sizes, const float* __restrict__ valid_scales)
{
    const int warp = (blockIdx.x * blockDim.x + threadIdx.x) >> 5;
    const int lane = threadIdx.x & 31;
    if (warp >= NB * SSQ * MM) return;

    const int m = warp & (MM - 1);
    const int q = (warp >> 3) % SSQ;
    const int n = warp / (SSQ * MM);

    const int lvl = (q < 10000) ? 0 : (q < 12500) ? 1 : (q < 13125) ? 2 : 3;
    const int Wl  = c_lvl_w[lvl];
    const int lq  = q - c_lvl_off[lvl];
    const float qxc = (float)(lq % Wl) + 0.5f;
    const float qyc = (float)(lq / Wl) + 0.5f;

    const float* row = g_offw + ((size_t)n * SSQ + q) * 96;

    // softmax over the 4 (f,p) logits for this head
    float lg[4];
#pragma unroll
    for (int f = 0; f < 4; f++) lg[f] = row[64 + m * 4 + f];
    float mx = fmaxf(fmaxf(lg[0], lg[1]), fmaxf(lg[2], lg[3]));
    float e[4];
    float ssum = 0.f;
#pragma unroll
    for (int f = 0; f < 4; f++) { e[f] = expf(lg[f] - mx); ssum += e[f]; }
    const float inv = 1.f / ssum;

    const float vsx = valid_sizes[(n * FLV + lvl) * 2 + 0];
    const float vsy = valid_sizes[(n * FLV + lvl) * 2 + 1];

    float acc0 = 0.f, acc1 = 0.f;
    const float* vbase = g_value + ((size_t)n * SSQ) * CCH + m * 64 + lane;

#pragma unroll
    for (int f = 0; f < 4; f++) {
        const float wf  = e[f] * inv;
        const float scx = 2.f * valid_scales[(n * FLV + f) * 2 + 0] / vsx;
        const float scy = 2.f * valid_scales[(n * FLV + f) * 2 + 1] / vsy;
        const float ox  = row[(m * 4 + f) * 2 + 0];
        const float oy  = row[(m * 4 + f) * 2 + 1];
        const float gx  = (ox + qxc) * scx - 1.f;
        const float gy  = (oy + qyc) * scy - 1.f;

        const int Wf = c_lvl_w[f];
        const int Hf = Wf;
        const float px = (gx + 1.f) * (Wf * 0.5f) - 0.5f;
        const float py = (gy + 1.f) * (Hf * 0.5f) - 0.5f;
        const float x0f = floorf(px), y0f = floorf(py);
        const int   x0 = (int)x0f,   y0 = (int)y0f;
        const float wx1 = px - x0f,  wy1 = py - y0f;
        const float wx0 = 1.f - wx1, wy0 = 1.f - wy1;
        const int base = c_lvl_off[f];

#pragma unroll
        for (int cy = 0; cy < 2; cy++) {
            const int yy = y0 + cy;
            if (yy < 0 || yy >= Hf) continue;
            const float wy = cy ? wy1 : wy0;
#pragma unroll
            for (int cx = 0; cx < 2; cx++) {
                const int xx = x0 + cx;
                if (xx < 0 || xx >= Wf) continue;
                const float wgt = wf * wy * (cx ? wx1 : wx0);
                const float* p = vbase + (size_t)(base + yy * Wf + xx) * CCH;
                acc0 = fmaf(wgt, p[0],  acc0);
                acc1 = fmaf(wgt, p[32], acc1);
            }
        }
    }

    float* o = g_samp + ((size_t)n * SSQ + q) * CCH + m * 64 + lane;
    o[0]  = acc0;
    o[32] = acc1;
}

// ---------------------------------------------------------------------------
// GEMM 3: out[n, o, s] = (sum_c Wo[o,c] * samp[n,s,c] + bo[o]) * scale[o]
// NT GEMM: both operands k(c)-contiguous. Tile 128(o) x 128(s).
// ---------------------------------------------------------------------------
__global__ void __launch_bounds__(256) k_gemm_out(
    const float* __restrict__ Wo, const float* __restrict__ bo,
    const float* __restrict__ scale, float* __restrict__ out)
{
    __shared__ float Ws[8][132];  // [k][o]
    __shared__ float Ss[8][132];  // [k][s]
    const int n  = blockIdx.z;
    const int s0 = blockIdx.x * 128;
    const int o0 = blockIdx.y * 128;
    const int t  = threadIdx.x;
    const int tx = t & 15;
    const int ty = t >> 4;

    float acc[8][8];
#pragma unroll
    for (int i = 0; i < 8; i++)
#pragma unroll
        for (int j = 0; j < 8; j++) acc[i][j] = 0.f;

    const int lr  = t >> 1;         // row index 0..127
    const int lk4 = (t & 1) << 2;   // 0 or 4

    for (int c0 = 0; c0 < CCH; c0 += 8) {
        float4 w4 = *(const float4*)(Wo + (size_t)(o0 + lr) * CCH + c0 + lk4);
        Ws[lk4 + 0][lr] = w4.x;
        Ws[lk4 + 1][lr] = w4.y;
        Ws[lk4 + 2][lr] = w4.z;
        Ws[lk4 + 3][lr] = w4.w;

        const int s = s0 + lr;
        float4 v4;
        if (s < SSQ) {
            v4 = *(const float4*)(g_samp + ((size_t)n * SSQ + s) * CCH + c0 + lk4);
        } else {
            v4 = make_float4(0.f, 0.f, 0.f, 0.f);
        }
        Ss[lk4 + 0][lr] = v4.x;
        Ss[lk4 + 1][lr] = v4.y;
        Ss[lk4 + 2][lr] = v4.z;
        Ss[lk4 + 3][lr] = v4.w;
        __syncthreads();

#pragma unroll
        for (int k = 0; k < 8; k++) {
            float a[8], b[8];
            *(float4*)&a[0] = *(const float4*)&Ws[k][ty * 8];
            *(float4*)&a[4] = *(const float4*)&Ws[k][ty * 8 + 4];
            *(float4*)&b[0] = *(const float4*)&Ss[k][tx * 4];
            *(float4*)&b[4] = *(const float4*)&Ss[k][64 + tx * 4];
#pragma unroll
            for (int i = 0; i < 8; i++)
#pragma unroll
                for (int j = 0; j < 8; j++)
                    acc[i][j] = fmaf(a[i], b[j], acc[i][j]);
        }
        __syncthreads();
    }

#pragma unroll
    for (int i = 0; i < 8; i++) {
        const int o = o0 + ty * 8 + i;
        const float bb = bo[o];
        const float sc = scale[o];
        float* dst = out + ((size_t)n * CCH + o) * SSQ;
#pragma unroll
        for (int h = 0; h < 2; h++) {
            const int sbase = s0 + h * 64 + tx * 4;
            float v[4];
#pragma unroll
            for (int j = 0; j < 4; j++) v[j] = (acc[i][h * 4 + j] + bb) * sc;
            if (sbase + 3 < SSQ) {
                *(float2*)(dst + sbase)     = make_float2(v[0], v[1]);
                *(float2*)(dst + sbase + 2) = make_float2(v[2], v[3]);
            } else {
#pragma unroll
                for (int j = 0; j < 4; j++)
                    if (sbase + j < SSQ) dst[sbase + j] = v[j];
            }
        }
    }
}

// ---------------------------------------------------------------------------
extern "C" void kernel_launch(void* const* d_in, const int* in_sizes, int n_in,
                              void* d_out, int out_size)
{
    const float* x            = (const float*)d_in[0];
    const float* pos          = (const float*)d_in[1];
    // d_in[2] = key_padding_mask (all false) — has no effect, skipped
    const float* valid_sizes  = (const float*)d_in[3];
    const float* valid_scales = (const float*)d_in[4];
    const float* Wv           = (const float*)d_in[5];
    const float* bv           = (const float*)d_in[6];
    const float* Wloc         = (const float*)d_in[7];
    const float* bloc         = (const float*)d_in[8];
    const float* Ww           = (const float*)d_in[9];
    const float* bw           = (const float*)d_in[10];
    const float* Wo           = (const float*)d_in[11];
    const float* bo           = (const float*)d_in[12];
    const float* scale        = (const float*)d_in[13];
    float* out = (float*)d_out;

    dim3 gA((SSQ + 127) / 128, CCH / 128, NB);   // 104 x 4 x 2
    k_gemm_value<<<gA, 256>>>(x, Wv, bv);

    dim3 gC((SSQ + 127) / 128, 1, NB);           // 104 x 1 x 2
    k_gemm_locw<<<gC, 256>>>(x, pos, Wloc, bloc, Ww, bw);

    const int nwarps = NB * SSQ * MM;            // 212704
    k_sample<<<(nwarps * 32 + 255) / 256, 256>>>(valid_sizes, valid_scales);

    k_gemm_out<<<gA, 256>>>(Wo, bo, scale, out);
}

// round 3
// speedup vs baseline: 1.0905x; 1.0905x over previous
#include <cuda_runtime.h>
#include <cstdint>

// Problem constants
#define NB   2
#define CCH  512
#define MM   8
#define FLV  4
#define SSQ  13294   // 10000 + 2500 + 625 + 169

__constant__ int c_lvl_off[4] = {0, 10000, 12500, 13125};
__constant__ int c_lvl_w[4]   = {100, 50, 25, 13};   // H == W per level

// Scratch (allocation-free rule => __device__ globals)
__device__ float g_value[(size_t)NB * SSQ * CCH];  // (n, s, c)  c-contiguous
__device__ float g_offw [(size_t)NB * SSQ * 96];   // (n, s, r)
__device__ float g_samp [(size_t)NB * SSQ * CCH];  // (n, s, c)

// ---------------------------------------------------------------------------
// Stage 1 (fused): blockIdx.y<4 -> value GEMM tile, blockIdx.y==4 -> locw GEMM
//
// value: value_t[n,s,o] = sum_c Wv[o,c] * x[n,c,s] + bv[o]     (128s x 128o)
// locw : offw[n,s,r]    = sum_c W[r,c] * (x+pos)[n,c,s] + b[r] (128s x 96r)
//
// Double-buffered SMEM, BK=8, one __syncthreads per K-chunk, LDG prefetch.
// x rows have stride SSQ=13294 (== 2 mod 4) -> only 8B alignment on
// s-contiguous loads: float2 only.
// ---------------------------------------------------------------------------
__global__ void __launch_bounds__(256) k_stage1(
    const float* __restrict__ x, const float* __restrict__ Wv,
    const float* __restrict__ bv,
    const float* __restrict__ pos,
    const float* __restrict__ Wloc, const float* __restrict__ bloc,
    const float* __restrict__ Ww,   const float* __restrict__ bw)
{
    __shared__ float As[2][8][132];  // [buf][k][s]
    __shared__ float Bs[2][8][132];  // [buf][k][o/r]

    const int n  = blockIdx.z;
    const int s0 = blockIdx.x * 128;
    const int t  = threadIdx.x;
    const int tx = t & 15;
    const int ty = t >> 4;

    const int lk  = t >> 5;          // 0..7
    const int ls4 = (t & 31) << 2;   // 0..124
    const int lo  = t >> 1;          // 0..127
    const int lk4 = (t & 1) << 2;    // 0 or 4

    const float* xn = x + (size_t)n * CCH * SSQ;
    const bool interior = (s0 + 124 + 3 < SSQ);

    if (blockIdx.y < 4) {
        // ----------------- value GEMM path -----------------
        const int o0 = blockIdx.y * 128;

        float acc[8][8];
#pragma unroll
        for (int i = 0; i < 8; i++)
#pragma unroll
            for (int j = 0; j < 8; j++) acc[i][j] = 0.f;

        float4 av, wv;
        // prologue: chunk 0
        {
            const float* srcA = xn + (size_t)lk * SSQ + s0 + ls4;
            if (interior) {
                float2 a0 = *(const float2*)(srcA);
                float2 a1 = *(const float2*)(srcA + 2);
                av = make_float4(a0.x, a0.y, a1.x, a1.y);
            } else {
                av.x = (s0 + ls4 + 0 < SSQ) ? srcA[0] : 0.f;
                av.y = (s0 + ls4 + 1 < SSQ) ? srcA[1] : 0.f;
                av.z = (s0 + ls4 + 2 < SSQ) ? srcA[2] : 0.f;
                av.w = (s0 + ls4 + 3 < SSQ) ? srcA[3] : 0.f;
            }
            wv = *(const float4*)(Wv + (size_t)(o0 + lo) * CCH + lk4);
        }
        *(float4*)&As[0][lk][ls4] = av;
        Bs[0][lk4 + 0][lo] = wv.x;
        Bs[0][lk4 + 1][lo] = wv.y;
        Bs[0][lk4 + 2][lo] = wv.z;
        Bs[0][lk4 + 3][lo] = wv.w;
        __syncthreads();

        int buf = 0;
#pragma unroll 1
        for (int c0 = 0; c0 < CCH; c0 += 8) {
            const bool has_next = (c0 + 8 < CCH);
            if (has_next) {
                const int cn = c0 + 8;
                const float* srcA = xn + (size_t)(cn + lk) * SSQ + s0 + ls4;
                if (interior) {
                    float2 a0 = *(const float2*)(srcA);
                    float2 a1 = *(const float2*)(srcA + 2);
                    av = make_float4(a0.x, a0.y, a1.x, a1.y);
                } else {
                    av.x = (s0 + ls4 + 0 < SSQ) ? srcA[0] : 0.f;
                    av.y = (s0 + ls4 + 1 < SSQ) ? srcA[1] : 0.f;
                    av.z = (s0 + ls4 + 2 < SSQ) ? srcA[2] : 0.f;
                    av.w = (s0 + ls4 + 3 < SSQ) ? srcA[3] : 0.f;
                }
                wv = *(const float4*)(Wv + (size_t)(o0 + lo) * CCH + cn + lk4);
            }

#pragma unroll
            for (int k = 0; k < 8; k++) {
                float a[8], b[8];
                *(float4*)&a[0] = *(const float4*)&As[buf][k][ty * 8];
                *(float4*)&a[4] = *(const float4*)&As[buf][k][ty * 8 + 4];
                *(float4*)&b[0] = *(const float4*)&Bs[buf][k][tx * 4];
                *(float4*)&b[4] = *(const float4*)&Bs[buf][k][64 + tx * 4];
#pragma unroll
                for (int i = 0; i < 8; i++)
#pragma unroll
                    for (int j = 0; j < 8; j++)
                        acc[i][j] = fmaf(a[i], b[j], acc[i][j]);
            }

            if (has_next) {
                const int nb = buf ^ 1;
                *(float4*)&As[nb][lk][ls4] = av;
                Bs[nb][lk4 + 0][lo] = wv.x;
                Bs[nb][lk4 + 1][lo] = wv.y;
                Bs[nb][lk4 + 2][lo] = wv.z;
                Bs[nb][lk4 + 3][lo] = wv.w;
                __syncthreads();
                buf = nb;
            }
        }

        float bias[8];
#pragma unroll
        for (int j = 0; j < 4; j++) {
            bias[j]     = bv[o0 + tx * 4 + j];
            bias[4 + j] = bv[o0 + 64 + tx * 4 + j];
        }
#pragma unroll
        for (int i = 0; i < 8; i++) {
            int s = s0 + ty * 8 + i;
            if (s < SSQ) {
                float* dst = g_value + ((size_t)n * SSQ + s) * CCH + o0;
                float4 v0 = make_float4(acc[i][0] + bias[0], acc[i][1] + bias[1],
                                        acc[i][2] + bias[2], acc[i][3] + bias[3]);
                float4 v1 = make_float4(acc[i][4] + bias[4], acc[i][5] + bias[5],
                                        acc[i][6] + bias[6], acc[i][7] + bias[7]);
                *(float4*)(dst + tx * 4)      = v0;
                *(float4*)(dst + 64 + tx * 4) = v1;
            }
        }
    } else {
        // ----------------- locw GEMM path -----------------
        const float* pn = pos + (size_t)n * CCH * SSQ;

        float acc[6][8];
#pragma unroll
        for (int i = 0; i < 6; i++)
#pragma unroll
            for (int j = 0; j < 8; j++) acc[i][j] = 0.f;

        const int lr = t >> 1;  // 0..127, valid < 96

        float4 av, wv;
        // prologue: chunk 0
        {
            size_t off = (size_t)lk * SSQ + s0 + ls4;
            if (interior) {
                float2 xa0 = *(const float2*)(xn + off);
                float2 xa1 = *(const float2*)(xn + off + 2);
                float2 pa0 = *(const float2*)(pn + off);
                float2 pa1 = *(const float2*)(pn + off + 2);
                av = make_float4(xa0.x + pa0.x, xa0.y + pa0.y,
                                 xa1.x + pa1.x, xa1.y + pa1.y);
            } else {
                av.x = (s0 + ls4 + 0 < SSQ) ? (xn[off + 0] + pn[off + 0]) : 0.f;
                av.y = (s0 + ls4 + 1 < SSQ) ? (xn[off + 1] + pn[off + 1]) : 0.f;
                av.z = (s0 + ls4 + 2 < SSQ) ? (xn[off + 2] + pn[off + 2]) : 0.f;
                av.w = (s0 + ls4 + 3 < SSQ) ? (xn[off + 3] + pn[off + 3]) : 0.f;
            }
            if (t < 192) {
                const float* wp = (lr < 64) ? (Wloc + (size_t)lr * CCH)
                                            : (Ww + (size_t)(lr - 64) * CCH);
                wv = *(const float4*)(wp + lk4);
            }
        }
        *(float4*)&As[0][lk][ls4] = av;
        if (t < 192) {
            Bs[0][lk4 + 0][lr] = wv.x;
            Bs[0][lk4 + 1][lr] = wv.y;
            Bs[0][lk4 + 2][lr] = wv.z;
            Bs[0][lk4 + 3][lr] = wv.w;
        }
        __syncthreads();

        int buf = 0;
#pragma unroll 1
        for (int c0 = 0; c0 < CCH; c0 += 8) {
            const bool has_next = (c0 + 8 < CCH);
            if (has_next) {
                const int cn = c0 + 8;
                size_t off = (size_t)(cn + lk) * SSQ + s0 + ls4;
                if (interior) {
                    float2 xa0 = *(const float2*)(xn + off);
                    float2 xa1 = *(const float2*)(xn + off + 2);
                    float2 pa0 = *(const float2*)(pn + off);
                    float2 pa1 = *(const float2*)(pn + off + 2);
                    av = make_float4(xa0.x + pa0.x, xa0.y + pa0.y,
                                     xa1.x + pa1.x, xa1.y + pa1.y);
                } else {
                    av.x = (s0 + ls4 + 0 < SSQ) ? (xn[off + 0] + pn[off + 0]) : 0.f;
                    av.y = (s0 + ls4 + 1 < SSQ) ? (xn[off + 1] + pn[off + 1]) : 0.f;
                    av.z = (s0 + ls4 + 2 < SSQ) ? (xn[off + 2] + pn[off + 2]) : 0.f;
                    av.w = (s0 + ls4 + 3 < SSQ) ? (xn[off + 3] + pn[off + 3]) : 0.f;
                }
                if (t < 192) {
                    const float* wp = (lr < 64) ? (Wloc + (size_t)lr * CCH)
                                                : (Ww + (size_t)(lr - 64) * CCH);
                    wv = *(const float4*)(wp + cn + lk4);
                }
            }

#pragma unroll
            for (int k = 0; k < 8; k++) {
                float a[8];
                *(float4*)&a[0] = *(const float4*)&As[buf][k][tx * 4];
                *(float4*)&a[4] = *(const float4*)&As[buf][k][64 + tx * 4];
                float b[6];
#pragma unroll
                for (int i = 0; i < 6; i++) b[i] = Bs[buf][k][ty * 6 + i];
#pragma unroll
                for (int i = 0; i < 6; i++)
#pragma unroll
                    for (int j = 0; j < 8; j++)
                        acc[i][j] = fmaf(b[i], a[j], acc[i][j]);
            }

            if (has_next) {
                const int nb = buf ^ 1;
                *(float4*)&As[nb][lk][ls4] = av;
                if (t < 192) {
                    Bs[nb][lk4 + 0][lr] = wv.x;
                    Bs[nb][lk4 + 1][lr] = wv.y;
                    Bs[nb][lk4 + 2][lr] = wv.z;
                    Bs[nb][lk4 + 3][lr] = wv.w;
                }
                __syncthreads();
                buf = nb;
            }
        }

#pragma unroll
        for (int i = 0; i < 6; i++) {
            int r = ty * 6 + i;
            float bb = (r < 64) ? bloc[r] : bw[r - 64];
#pragma unroll
            for (int j = 0; j < 8; j++) {
                int s = s0 + ((j < 4) ? (tx * 4 + j) : (64 + tx * 4 + (j - 4)));
                if (s < SSQ)
                    g_offw[((size_t)n * SSQ + s) * 96 + r] = acc[i][j] + bb;
            }
        }
    }
}

// ---------------------------------------------------------------------------
// Sampling: one warp per (n, q, m). 64 channels per head -> lane and lane+32.
// ---------------------------------------------------------------------------
__global__ void __launch_bounds__(256) k_sample(
    const float* __restrict__ valid_sizes, const float* __restrict__ valid_scales)
{
    const int warp = (blockIdx.x * blockDim.x + threadIdx.x) >> 5;
    const int lane = threadIdx.x & 31;
    if (warp >= NB * SSQ * MM) return;

    const int m = warp & (MM - 1);
    const int q = (warp >> 3) % SSQ;
    const int n = warp / (SSQ * MM);

    const int lvl = (q < 10000) ? 0 : (q < 12500) ? 1 : (q < 13125) ? 2 : 3;
    const int Wl  = c_lvl_w[lvl];
    const int lq  = q - c_lvl_off[lvl];
    const float qxc = (float)(lq % Wl) + 0.5f;
    const float qyc = (float)(lq / Wl) + 0.5f;

    const float* row = g_offw + ((size_t)n * SSQ + q) * 96;

    float lg[4];
#pragma unroll
    for (int f = 0; f < 4; f++) lg[f] = row[64 + m * 4 + f];
    float mx = fmaxf(fmaxf(lg[0], lg[1]), fmaxf(lg[2], lg[3]));
    float e[4];
    float ssum = 0.f;
#pragma unroll
    for (int f = 0; f < 4; f++) { e[f] = expf(lg[f] - mx); ssum += e[f]; }
    const float inv = 1.f / ssum;

    const float vsx = valid_sizes[(n * FLV + lvl) * 2 + 0];
    const float vsy = valid_sizes[(n * FLV + lvl) * 2 + 1];

    float acc0 = 0.f, acc1 = 0.f;
    const float* vbase = g_value + ((size_t)n * SSQ) * CCH + m * 64 + lane;

#pragma unroll
    for (int f = 0; f < 4; f++) {
        const float wf  = e[f] * inv;
        const float scx = 2.f * valid_scales[(n * FLV + f) * 2 + 0] / vsx;
        const float scy = 2.f * valid_scales[(n * FLV + f) * 2 + 1] / vsy;
        const float ox  = row[(m * 4 + f) * 2 + 0];
        const float oy  = row[(m * 4 + f) * 2 + 1];
        const float gx  = (ox + qxc) * scx - 1.f;
        const float gy  = (oy + qyc) * scy - 1.f;

        const int Wf = c_lvl_w[f];
        const int Hf = Wf;
        const float px = (gx + 1.f) * (Wf * 0.5f) - 0.5f;
        const float py = (gy + 1.f) * (Hf * 0.5f) - 0.5f;
        const float x0f = floorf(px), y0f = floorf(py);
        const int   x0 = (int)x0f,   y0 = (int)y0f;
        const float wx1 = px - x0f,  wy1 = py - y0f;
        const float wx0 = 1.f - wx1, wy0 = 1.f - wy1;
        const int base = c_lvl_off[f];

#pragma unroll
        for (int cy = 0; cy < 2; cy++) {
            const int yy = y0 + cy;
            if (yy < 0 || yy >= Hf) continue;
            const float wy = cy ? wy1 : wy0;
#pragma unroll
            for (int cx = 0; cx < 2; cx++) {
                const int xx = x0 + cx;
                if (xx < 0 || xx >= Wf) continue;
                const float wgt = wf * wy * (cx ? wx1 : wx0);
                const float* p = vbase + (size_t)(base + yy * Wf + xx) * CCH;
                acc0 = fmaf(wgt, p[0],  acc0);
                acc1 = fmaf(wgt, p[32], acc1);
            }
        }
    }

    float* o = g_samp + ((size_t)n * SSQ + q) * CCH + m * 64 + lane;
    o[0]  = acc0;
    o[32] = acc1;
}

// ---------------------------------------------------------------------------
// GEMM 3: out[n, o, s] = (sum_c Wo[o,c] * samp[n,s,c] + bo[o]) * scale[o]
// NT GEMM, 128(o) x 128(s), double-buffered, one sync per chunk.
// ---------------------------------------------------------------------------
__global__ void __launch_bounds__(256) k_gemm_out(
    const float* __restrict__ Wo, const float* __restrict__ bo,
    const float* __restrict__ scale, float* __restrict__ out)
{
    __shared__ float Ws[2][8][132];  // [buf][k][o]
    __shared__ float Ss[2][8][132];  // [buf][k][s]
    const int n  = blockIdx.z;
    const int s0 = blockIdx.x * 128;
    const int o0 = blockIdx.y * 128;
    const int t  = threadIdx.x;
    const int tx = t & 15;
    const int ty = t >> 4;

    float acc[8][8];
#pragma unroll
    for (int i = 0; i < 8; i++)
#pragma unroll
        for (int j = 0; j < 8; j++) acc[i][j] = 0.f;

    const int lr  = t >> 1;         // row index 0..127
    const int lk4 = (t & 1) << 2;   // 0 or 4
    const int sidx = s0 + lr;
    const bool svalid = (sidx < SSQ);
    const float* srow = g_samp + ((size_t)n * SSQ + (svalid ? sidx : 0)) * CCH;
    const float* wrow = Wo + (size_t)(o0 + lr) * CCH;

    float4 w4, v4;
    // prologue chunk 0
    w4 = *(const float4*)(wrow + lk4);
    v4 = svalid ? *(const float4*)(srow + lk4) : make_float4(0.f, 0.f, 0.f, 0.f);
    Ws[0][lk4 + 0][lr] = w4.x; Ws[0][lk4 + 1][lr] = w4.y;
    Ws[0][lk4 + 2][lr] = w4.z; Ws[0][lk4 + 3][lr] = w4.w;
    Ss[0][lk4 + 0][lr] = v4.x; Ss[0][lk4 + 1][lr] = v4.y;
    Ss[0][lk4 + 2][lr] = v4.z; Ss[0][lk4 + 3][lr] = v4.w;
    __syncthreads();

    int buf = 0;
#pragma unroll 1
    for (int c0 = 0; c0 < CCH; c0 += 8) {
        const bool has_next = (c0 + 8 < CCH);
        if (has_next) {
            const int cn = c0 + 8;
            w4 = *(const float4*)(wrow + cn + lk4);
            v4 = svalid ? *(const float4*)(srow + cn + lk4)
                        : make_float4(0.f, 0.f, 0.f, 0.f);
        }

#pragma unroll
        for (int k = 0; k < 8; k++) {
            float a[8], b[8];
            *(float4*)&a[0] = *(const float4*)&Ws[buf][k][ty * 8];
            *(float4*)&a[4] = *(const float4*)&Ws[buf][k][ty * 8 + 4];
            *(float4*)&b[0] = *(const float4*)&Ss[buf][k][tx * 4];
            *(float4*)&b[4] = *(const float4*)&Ss[buf][k][64 + tx * 4];
#pragma unroll
            for (int i = 0; i < 8; i++)
#pragma unroll
                for (int j = 0; j < 8; j++)
                    acc[i][j] = fmaf(a[i], b[j], acc[i][j]);
        }

        if (has_next) {
            const int nb = buf ^ 1;
            Ws[nb][lk4 + 0][lr] = w4.x; Ws[nb][lk4 + 1][lr] = w4.y;
            Ws[nb][lk4 + 2][lr] = w4.z; Ws[nb][lk4 + 3][lr] = w4.w;
            Ss[nb][lk4 + 0][lr] = v4.x; Ss[nb][lk4 + 1][lr] = v4.y;
            Ss[nb][lk4 + 2][lr] = v4.z; Ss[nb][lk4 + 3][lr] = v4.w;
            __syncthreads();
            buf = nb;
        }
    }

#pragma unroll
    for (int i = 0; i < 8; i++) {
        const int o = o0 + ty * 8 + i;
        const float bb = bo[o];
        const float sc = scale[o];
        float* dst = out + ((size_t)n * CCH + o) * SSQ;
#pragma unroll
        for (int h = 0; h < 2; h++) {
            const int sbase = s0 + h * 64 + tx * 4;
            float v[4];
#pragma unroll
            for (int j = 0; j < 4; j++) v[j] = (acc[i][h * 4 + j] + bb) * sc;
            if (sbase + 3 < SSQ) {
                *(float2*)(dst + sbase)     = make_float2(v[0], v[1]);
                *(float2*)(dst + sbase + 2) = make_float2(v[2], v[3]);
            } else {
#pragma unroll
                for (int j = 0; j < 4; j++)
                    if (sbase + j < SSQ) dst[sbase + j] = v[j];
            }
        }
    }
}

// ---------------------------------------------------------------------------
extern "C" void kernel_launch(void* const* d_in, const int* in_sizes, int n_in,
                              void* d_out, int out_size)
{
    const float* x            = (const float*)d_in[0];
    const float* pos          = (const float*)d_in[1];
    // d_in[2] = key_padding_mask (all false) — no effect, skipped
    const float* valid_sizes  = (const float*)d_in[3];
    const float* valid_scales = (const float*)d_in[4];
    const float* Wv           = (const float*)d_in[5];
    const float* bv           = (const float*)d_in[6];
    const float* Wloc         = (const float*)d_in[7];
    const float* bloc         = (const float*)d_in[8];
    const float* Ww           = (const float*)d_in[9];
    const float* bw           = (const float*)d_in[10];
    const float* Wo           = (const float*)d_in[11];
    const float* bo           = (const float*)d_in[12];
    const float* scale        = (const float*)d_in[13];
    float* out = (float*)d_out;

    dim3 g1((SSQ + 127) / 128, 5, NB);   // y<4: value tiles, y==4: locw
    k_stage1<<<g1, 256>>>(x, Wv, bv, pos, Wloc, bloc, Ww, bw);

    const int nwarps = NB * SSQ * MM;    // 212704
    k_sample<<<(nwarps * 32 + 255) / 256, 256>>>(valid_sizes, valid_scales);

    dim3 g3((SSQ + 127) / 128, CCH / 128, NB);
    k_gemm_out<<<g3, 256>>>(Wo, bo, scale, out);
}

// round 6
// speedup vs baseline: 1.9632x; 1.8002x over previous
#include <cuda_runtime.h>
#include <cuda_bf16.h>
#include <cstdint>

#define NB   2
#define CCH  512
#define MM   8
#define FLV  4
#define SSQ  13294
#define SPAD 13312            // 104*128
#define KCH  32               // K per chunk (bf16)
#define NCH  (CCH/KCH)        // 16
#define ROWB 80               // padded smem row stride bytes (40 bf16), 16B-aligned rows
#define ASZ  (128*ROWB)       // 10240 B per operand array
#define STG  (4*ASZ)          // 40960 B per stage {Ah,Al,Bh,Bl}
#define SMEM_SZ (2*STG)       // 81920 (also covers 128x132 f32 epilogue = 67584)

__constant__ int c_lvl_off[4] = {0, 10000, 12500, 13125};
__constant__ int c_lvl_w[4]   = {100, 50, 25, 13};

// ---------------- device scratch ----------------
__device__ __align__(128) __nv_bfloat16 g_xT_hi [(size_t)NB * SPAD * CCH];
__device__ __align__(128) __nv_bfloat16 g_xT_lo [(size_t)NB * SPAD * CCH];
__device__ __align__(128) __nv_bfloat16 g_xpT_hi[(size_t)NB * SPAD * CCH];
__device__ __align__(128) __nv_bfloat16 g_xpT_lo[(size_t)NB * SPAD * CCH];
__device__ __align__(128) __nv_bfloat16 g_W1h[CCH * CCH], g_W1l[CCH * CCH];
__device__ __align__(128) __nv_bfloat16 g_Woh[CCH * CCH], g_Wol[CCH * CCH];
__device__ __align__(128) __nv_bfloat16 g_Wlwh[128 * CCH], g_Wlwl[128 * CCH];  // rows 96..127 stay 0
__device__ float g_blw[96];
__device__ __align__(128) float g_value[(size_t)NB * SSQ * CCH];   // (n,s,c) fp32
__device__ __align__(128) float g_offw [(size_t)NB * SSQ * 96];
__device__ __align__(128) __nv_bfloat16 g_smp_hi[(size_t)NB * SPAD * CCH];
__device__ __align__(128) __nv_bfloat16 g_smp_lo[(size_t)NB * SPAD * CCH];

// ---------------- PTX helpers (base sm_103 ISA only) ----------------
__device__ __forceinline__ uint32_t smem_u32(const void* p) {
    uint32_t a;
    asm("{ .reg .u64 t; cvta.to.shared.u64 t, %1; cvt.u32.u64 %0, t; }" : "=r"(a) : "l"(p));
    return a;
}
__device__ __forceinline__ void cpa16(uint32_t s, const void* g) {
    asm volatile("cp.async.cg.shared.global [%0], [%1], 16;" :: "r"(s), "l"(g));
}
#define CP_COMMIT() asm volatile("cp.async.commit_group;" ::: "memory")
#define CP_WAIT1()  asm volatile("cp.async.wait_group 1;" ::: "memory")
#define CP_WAIT0()  asm volatile("cp.async.wait_group 0;" ::: "memory")

#define LDSM4(r0, r1, r2, r3, adr) \
    asm volatile("ldmatrix.sync.aligned.m8n8.x4.shared.b16 {%0,%1,%2,%3}, [%4];" \
        : "=r"(r0), "=r"(r1), "=r"(r2), "=r"(r3) : "r"(adr))

#define MMA_BF16(d, a, b) \
    asm volatile("mma.sync.aligned.m16n8k16.row.col.f32.bf16.bf16.f32 " \
        "{%0,%1,%2,%3}, {%4,%5,%6,%7}, {%8,%9}, {%0,%1,%2,%3};" \
        : "+f"((d)[0]), "+f"((d)[1]), "+f"((d)[2]), "+f"((d)[3]) \
        : "r"((a)[0]), "r"((a)[1]), "r"((a)[2]), "r"((a)[3]), \
          "r"((b)[0]), "r"((b)[1]))

// ---------------------------------------------------------------------------
// transpose + bf16 hi/lo convert: x(n,c,s) -> xT(n,s,c); (x+pos) likewise
// ---------------------------------------------------------------------------
__global__ void __launch_bounds__(256) k_transpose(
    const float* __restrict__ x, const float* __restrict__ pos)
{
    __shared__ float tx_[32][33], tp_[32][33];
    const int n = blockIdx.z, c0 = blockIdx.y * 32, s0 = blockIdx.x * 32;
    const int ti = threadIdx.x, tj = threadIdx.y;  // (32, 8)
    const float* xb = x   + ((size_t)n * CCH + c0) * SSQ;
    const float* pb = pos + ((size_t)n * CCH + c0) * SSQ;
#pragma unroll
    for (int k = 0; k < 4; k++) {
        const int cl = tj + 8 * k, s = s0 + ti;
        float xv = 0.f, pv = 0.f;
        if (s < SSQ) { xv = xb[(size_t)cl * SSQ + s]; pv = pb[(size_t)cl * SSQ + s]; }
        tx_[cl][ti] = xv;
        tp_[cl][ti] = xv + pv;
    }
    __syncthreads();
#pragma unroll
    for (int k = 0; k < 4; k++) {
        const int s = s0 + tj + 8 * k, c = c0 + ti;
        float xv = tx_[ti][tj + 8 * k];
        float pv = tp_[ti][tj + 8 * k];
        if (s >= SSQ) { xv = 0.f; pv = 0.f; }
        const size_t o = ((size_t)n * SPAD + s) * CCH + c;
        __nv_bfloat16 h = __float2bfloat16(xv);
        g_xT_hi[o] = h;
        g_xT_lo[o] = __float2bfloat16(xv - __bfloat162float(h));
        h = __float2bfloat16(pv);
        g_xpT_hi[o] = h;
        g_xpT_lo[o] = __float2bfloat16(pv - __bfloat162float(h));
    }
}

// ---------------------------------------------------------------------------
// weight convert
// ---------------------------------------------------------------------------
__global__ void __launch_bounds__(256) k_wconv(
    const float* __restrict__ Wv, const float* __restrict__ Wo,
    const float* __restrict__ Wloc, const float* __restrict__ Ww,
    const float* __restrict__ bloc, const float* __restrict__ bw)
{
    const int i = blockIdx.x * 256 + threadIdx.x;
    if (i < CCH * CCH) {
        float v = Wv[i];
        __nv_bfloat16 h = __float2bfloat16(v);
        g_W1h[i] = h; g_W1l[i] = __float2bfloat16(v - __bfloat162float(h));
        v = Wo[i];
        h = __float2bfloat16(v);
        g_Woh[i] = h; g_Wol[i] = __float2bfloat16(v - __bfloat162float(h));
    }
    if (i < 96 * CCH) {
        const int r = i >> 9, c = i & 511;
        const float v = (r < 64) ? Wloc[r * 512 + c] : Ww[(r - 64) * 512 + c];
        __nv_bfloat16 h = __float2bfloat16(v);
        g_Wlwh[i] = h; g_Wlwl[i] = __float2bfloat16(v - __bfloat162float(h));
    }
    if (i < 96) g_blw[i] = (i < 64) ? bloc[i] : bw[i - 64];
}

// ---------------------------------------------------------------------------
// bf16x3 HMMA mainloop: acc[2][8][4] (warp tile 32m x 64n), A/B k-major bf16,
// 2-stage cp.async pipeline, K = 512.
// ---------------------------------------------------------------------------
__device__ __forceinline__ void hmma_mainloop(
    uint32_t smem,
    const __nv_bfloat16* __restrict__ Ah, const __nv_bfloat16* __restrict__ Al,
    const __nv_bfloat16* __restrict__ Bh, const __nv_bfloat16* __restrict__ Bl,
    float acc[2][8][4])
{
    const int t = threadIdx.x;
    const int lane = t & 31, wid = t >> 5;
    const int wm = (wid & 3) * 32, wn = (wid >> 2) * 64;

    auto issue = [&](int st, int c0) {
        const uint32_t sb = smem + st * STG;
#pragma unroll
        for (int r = 0; r < 2; r++) {
            const int id  = t + 256 * r;
            const int row = id >> 2;
            const int kc  = id & 3;
            const uint32_t so = row * ROWB + kc * 16;
            const size_t go = (size_t)row * CCH + c0 + kc * 8;
            cpa16(sb + 0 * ASZ + so, Ah + go);
            cpa16(sb + 1 * ASZ + so, Al + go);
            cpa16(sb + 2 * ASZ + so, Bh + go);
            cpa16(sb + 3 * ASZ + so, Bl + go);
        }
    };

    issue(0, 0);
    CP_COMMIT();

#pragma unroll 1
    for (int ch = 0; ch < NCH; ch++) {
        if (ch + 1 < NCH) {
            issue((ch + 1) & 1, (ch + 1) * KCH);
            CP_COMMIT();
            CP_WAIT1();
        } else {
            CP_WAIT0();
        }
        __syncthreads();

        const uint32_t sb = smem + (ch & 1) * STG;
        const uint32_t sAh = sb, sAl = sb + ASZ, sBh = sb + 2 * ASZ, sBl = sb + 3 * ASZ;

#pragma unroll
        for (int ks = 0; ks < 2; ks++) {
            const int k16 = ks * 16;
            uint32_t ah[2][4], al[2][4], bh[8][2], bl[8][2];

            // A frags: row = wm + m*16 + (lane&15), col = k16 + (lane>>4)*8
            const uint32_t aoff = (wm + (lane & 15)) * ROWB +
                                  (k16 + ((lane >> 4) << 3)) * 2;
#pragma unroll
            for (int m = 0; m < 2; m++) {
                const uint32_t ao = aoff + m * 16 * ROWB;
                LDSM4(ah[m][0], ah[m][1], ah[m][2], ah[m][3], sAh + ao);
                LDSM4(al[m][0], al[m][1], al[m][2], al[m][3], sAl + ao);
            }
            // B frags
            const uint32_t brow = (lane & 7) + ((lane & 16) >> 1);
            const uint32_t bcol = (k16 + (((lane >> 3) & 1) << 3)) * 2;
#pragma unroll
            for (int p = 0; p < 4; p++) {
                const uint32_t bo = (wn + p * 16 + brow) * ROWB + bcol;
                LDSM4(bh[2 * p][0], bh[2 * p][1], bh[2 * p + 1][0], bh[2 * p + 1][1], sBh + bo);
                LDSM4(bl[2 * p][0], bl[2 * p][1], bl[2 * p + 1][0], bl[2 * p + 1][1], sBl + bo);
            }

            // three passes: hh, hl, lh — dependency distance 16
#pragma unroll
            for (int m = 0; m < 2; m++)
#pragma unroll
                for (int ni = 0; ni < 8; ni++) MMA_BF16(acc[m][ni], ah[m], bh[ni]);
#pragma unroll
            for (int m = 0; m < 2; m++)
#pragma unroll
                for (int ni = 0; ni < 8; ni++) MMA_BF16(acc[m][ni], ah[m], bl[ni]);
#pragma unroll
            for (int m = 0; m < 2; m++)
#pragma unroll
                for (int ni = 0; ni < 8; ni++) MMA_BF16(acc[m][ni], al[m], bh[ni]);
        }
        __syncthreads();
    }
}

// ---------------------------------------------------------------------------
// GEMM kernel 1: y<4 -> value tile (B = Wv rows o0..o0+127),
//                y==4 -> locw (B = Wlw, 96 valid rows)
// ---------------------------------------------------------------------------
__global__ void __launch_bounds__(256) k_mma1(const float* __restrict__ bv)
{
    extern __shared__ char smc[];
    const uint32_t smem = smem_u32(smc);
    const int t = threadIdx.x, lane = t & 31, wid = t >> 5;
    const int wm = (wid & 3) * 32, wn = (wid >> 2) * 64;
    const int n = blockIdx.z, yt = blockIdx.y, s0 = blockIdx.x * 128;

    float acc[2][8][4];
#pragma unroll
    for (int m = 0; m < 2; m++)
#pragma unroll
        for (int ni = 0; ni < 8; ni++)
#pragma unroll
            for (int j = 0; j < 4; j++) acc[m][ni][j] = 0.f;

    const size_t aoff = ((size_t)n * SPAD + s0) * CCH;
    if (yt < 4) {
        hmma_mainloop(smem, g_xT_hi + aoff, g_xT_lo + aoff,
                      g_W1h + (size_t)yt * 128 * CCH, g_W1l + (size_t)yt * 128 * CCH, acc);
        const int o0 = yt * 128;
#pragma unroll
        for (int m = 0; m < 2; m++) {
            const int r0 = s0 + wm + m * 16 + (lane >> 2);
            const int r1 = r0 + 8;
#pragma unroll
            for (int ni = 0; ni < 8; ni++) {
                const int col = o0 + wn + ni * 8 + (lane & 3) * 2;
                const float b0 = bv[col], b1 = bv[col + 1];
                if (r0 < SSQ) {
                    float2 v = make_float2(acc[m][ni][0] + b0, acc[m][ni][1] + b1);
                    *(float2*)(g_value + ((size_t)n * SSQ + r0) * CCH + col) = v;
                }
                if (r1 < SSQ) {
                    float2 v = make_float2(acc[m][ni][2] + b0, acc[m][ni][3] + b1);
                    *(float2*)(g_value + ((size_t)n * SSQ + r1) * CCH + col) = v;
                }
            }
        }
    } else {
        hmma_mainloop(smem, g_xpT_hi + aoff, g_xpT_lo + aoff, g_Wlwh, g_Wlwl, acc);
#pragma unroll
        for (int m = 0; m < 2; m++) {
            const int r0 = s0 + wm + m * 16 + (lane >> 2);
            const int r1 = r0 + 8;
#pragma unroll
            for (int ni = 0; ni < 8; ni++) {
                const int col = wn + ni * 8 + (lane & 3) * 2;
                if (col >= 96) continue;
                const float b0 = g_blw[col], b1 = g_blw[col + 1];
                if (r0 < SSQ) {
                    float2 v = make_float2(acc[m][ni][0] + b0, acc[m][ni][1] + b1);
                    *(float2*)(g_offw + ((size_t)n * SSQ + r0) * 96 + col) = v;
                }
                if (r1 < SSQ) {
                    float2 v = make_float2(acc[m][ni][2] + b0, acc[m][ni][3] + b1);
                    *(float2*)(g_offw + ((size_t)n * SSQ + r1) * 96 + col) = v;
                }
            }
        }
    }
}

// ---------------------------------------------------------------------------
// GEMM kernel 2: out[n, o, s] = (samp[s,:]·Wo[o,:] + bo[o]) * scale[o]
// SMEM transpose epilogue for coalesced (o, s) stores.
// ---------------------------------------------------------------------------
__global__ void __launch_bounds__(256) k_mma2(
    const float* __restrict__ bo, const float* __restrict__ scale,
    float* __restrict__ out)
{
    extern __shared__ char smc[];
    const uint32_t smem = smem_u32(smc);
    const int t = threadIdx.x, lane = t & 31, wid = t >> 5;
    const int wm = (wid & 3) * 32, wn = (wid >> 2) * 64;
    const int n = blockIdx.z, s0 = blockIdx.x * 128, o0 = blockIdx.y * 128;

    float acc[2][8][4];
#pragma unroll
    for (int m = 0; m < 2; m++)
#pragma unroll
        for (int ni = 0; ni < 8; ni++)
#pragma unroll
            for (int j = 0; j < 4; j++) acc[m][ni][j] = 0.f;

    const size_t aoff = ((size_t)n * SPAD + s0) * CCH;
    hmma_mainloop(smem, g_smp_hi + aoff, g_smp_lo + aoff,
                  g_Woh + (size_t)o0 * CCH, g_Wol + (size_t)o0 * CCH, acc);

    __syncthreads();
    // stage to smem [128 s][132 o], then transposed coalesced store
    float* ss = (float*)smc;
#pragma unroll
    for (int m = 0; m < 2; m++) {
        const int r0 = wm + m * 16 + (lane >> 2);
#pragma unroll
        for (int ni = 0; ni < 8; ni++) {
            const int col = wn + ni * 8 + (lane & 3) * 2;
            ss[r0 * 132 + col]           = acc[m][ni][0];
            ss[r0 * 132 + col + 1]       = acc[m][ni][1];
            ss[(r0 + 8) * 132 + col]     = acc[m][ni][2];
            ss[(r0 + 8) * 132 + col + 1] = acc[m][ni][3];
        }
    }
    __syncthreads();

    const int o  = t & 127;
    const int sh = (t >> 7) * 64;
    const float bb = bo[o0 + o], sc = scale[o0 + o];
    float* dst = out + ((size_t)n * CCH + o0 + o) * SSQ;
#pragma unroll
    for (int j = 0; j < 32; j++) {
        const int s = sh + j * 2, gs = s0 + s;
        const float v0 = (ss[s * 132 + o] + bb) * sc;
        const float v1 = (ss[(s + 1) * 132 + o] + bb) * sc;
        if (gs + 1 < SSQ) {
            *(float2*)(dst + gs) = make_float2(v0, v1);
        } else {
            if (gs < SSQ) dst[gs] = v0;
        }
    }
}

// ---------------------------------------------------------------------------
// Sampling: one warp per (n, q, m); outputs bf16 hi/lo for GEMM2's A operand.
// ---------------------------------------------------------------------------
__global__ void __launch_bounds__(256) k_sample(
    const float* __restrict__ valid_sizes, const float* __restrict__ valid_scales)
{
    const int warp = (blockIdx.x * blockDim.x + threadIdx.x) >> 5;
    const int lane = threadIdx.x & 31;
    if (warp >= NB * SSQ * MM) return;

    const int m = warp & (MM - 1);
    const int q = (warp >> 3) % SSQ;
    const int n = warp / (SSQ * MM);

    const int lvl = (q < 10000) ? 0 : (q < 12500) ? 1 : (q < 13125) ? 2 : 3;
    const int Wl  = c_lvl_w[lvl];
    const int lq  = q - c_lvl_off[lvl];
    const float qxc = (float)(lq % Wl) + 0.5f;
    const float qyc = (float)(lq / Wl) + 0.5f;

    const float* row = g_offw + ((size_t)n * SSQ + q) * 96;

    float lg[4];
#pragma unroll
    for (int f = 0; f < 4; f++) lg[f] = row[64 + m * 4 + f];
    float mx = fmaxf(fmaxf(lg[0], lg[1]), fmaxf(lg[2], lg[3]));
    float e[4], ssum = 0.f;
#pragma unroll
    for (int f = 0; f < 4; f++) { e[f] = expf(lg[f] - mx); ssum += e[f]; }
    const float inv = 1.f / ssum;

    const float vsx = valid_sizes[(n * FLV + lvl) * 2 + 0];
    const float vsy = valid_sizes[(n * FLV + lvl) * 2 + 1];

    float acc0 = 0.f, acc1 = 0.f;
    const float* vbase = g_value + ((size_t)n * SSQ) * CCH + m * 64 + lane;

#pragma unroll
    for (int f = 0; f < 4; f++) {
        const float wf  = e[f] * inv;
        const float scx = 2.f * valid_scales[(n * FLV + f) * 2 + 0] / vsx;
        const float scy = 2.f * valid_scales[(n * FLV + f) * 2 + 1] / vsy;
        const float ox  = row[(m * 4 + f) * 2 + 0];
        const float oy  = row[(m * 4 + f) * 2 + 1];
        const float gx  = (ox + qxc) * scx - 1.f;
        const float gy  = (oy + qyc) * scy - 1.f;

        const int Wf = c_lvl_w[f], Hf = Wf;
        const float px = (gx + 1.f) * (Wf * 0.5f) - 0.5f;
        const float py = (gy + 1.f) * (Hf * 0.5f) - 0.5f;
        const float x0f = floorf(px), y0f = floorf(py);
        const int   x0 = (int)x0f,   y0 = (int)y0f;
        const float wx1 = px - x0f,  wy1 = py - y0f;
        const float wx0 = 1.f - wx1, wy0 = 1.f - wy1;
        const int base = c_lvl_off[f];

#pragma unroll
        for (int cy = 0; cy < 2; cy++) {
            const int yy = y0 + cy;
            if (yy < 0 || yy >= Hf) continue;
            const float wy = cy ? wy1 : wy0;
#pragma unroll
            for (int cx = 0; cx < 2; cx++) {
                const int xx = x0 + cx;
                if (xx < 0 || xx >= Wf) continue;
                const float wgt = wf * wy * (cx ? wx1 : wx0);
                const float* p = vbase + (size_t)(base + yy * Wf + xx) * CCH;
                acc0 = fmaf(wgt, p[0],  acc0);
                acc1 = fmaf(wgt, p[32], acc1);
            }
        }
    }

    const size_t ob = ((size_t)n * SPAD + q) * CCH + m * 64 + lane;
    __nv_bfloat16 h0 = __float2bfloat16(acc0);
    g_smp_hi[ob] = h0;
    g_smp_lo[ob] = __float2bfloat16(acc0 - __bfloat162float(h0));
    __nv_bfloat16 h1 = __float2bfloat16(acc1);
    g_smp_hi[ob + 32] = h1;
    g_smp_lo[ob + 32] = __float2bfloat16(acc1 - __bfloat162float(h1));
}

// ---------------------------------------------------------------------------
extern "C" void kernel_launch(void* const* d_in, const int* in_sizes, int n_in,
                              void* d_out, int out_size)
{
    const float* x            = (const float*)d_in[0];
    const float* pos          = (const float*)d_in[1];
    const float* valid_sizes  = (const float*)d_in[3];
    const float* valid_scales = (const float*)d_in[4];
    const float* Wv           = (const float*)d_in[5];
    const float* bv           = (const float*)d_in[6];
    const float* Wloc         = (const float*)d_in[7];
    const float* bloc         = (const float*)d_in[8];
    const float* Ww           = (const float*)d_in[9];
    const float* bw           = (const float*)d_in[10];
    const float* Wo           = (const float*)d_in[11];
    const float* bo           = (const float*)d_in[12];
    const float* scale        = (const float*)d_in[13];
    float* out = (float*)d_out;

    static bool attr_set = false;
    if (!attr_set) {
        cudaFuncSetAttribute(k_mma1, cudaFuncAttributeMaxDynamicSharedMemorySize, SMEM_SZ);
        cudaFuncSetAttribute(k_mma2, cudaFuncAttributeMaxDynamicSharedMemorySize, SMEM_SZ);
        attr_set = true;
    }

    dim3 gt(SPAD / 32, CCH / 32, NB);
    k_transpose<<<gt, dim3(32, 8)>>>(x, pos);

    k_wconv<<<(CCH * CCH) / 256, 256>>>(Wv, Wo, Wloc, Ww, bloc, bw);

    dim3 g1(SPAD / 128, 5, NB);
    k_mma1<<<g1, 256, SMEM_SZ>>>(bv);

    const int nwarps = NB * SSQ * MM;
    k_sample<<<(nwarps * 32 + 255) / 256, 256>>>(valid_sizes, valid_scales);

    dim3 g2(SPAD / 128, CCH / 128, NB);
    k_mma2<<<g2, 256, SMEM_SZ>>>(bo, scale, out);
}

// round 9
// speedup vs baseline: 1.9804x; 1.0087x over previous
#include <cuda_runtime.h>
#include <cuda_bf16.h>
#include <cstdint>

#define NB   2
#define CCH  512
#define MM   8
#define FLV  4
#define SSQ  13294
#define SPAD 13312            // 104*128
#define KCH  32               // K per chunk (bf16)
#define NCH  (CCH/KCH)        // 16
#define ROWB 80               // padded smem row stride bytes (40 bf16), 16B-aligned rows
#define ASZ  (128*ROWB)       // 10240 B per operand array
#define STG  (4*ASZ)          // 40960 B per stage {Ah,Al,Bh,Bl}
#define SMEM_SZ (2*STG)       // 81920 (also covers 128x132 f32 epilogue = 67584)

__constant__ int c_lvl_off[4] = {0, 10000, 12500, 13125};
__constant__ int c_lvl_w[4]   = {100, 50, 25, 13};

// ---------------- device scratch ----------------
__device__ __align__(128) __nv_bfloat16 g_xT_hi [(size_t)NB * SPAD * CCH];
__device__ __align__(128) __nv_bfloat16 g_xT_lo [(size_t)NB * SPAD * CCH];
__device__ __align__(128) __nv_bfloat16 g_xpT_hi[(size_t)NB * SPAD * CCH];
__device__ __align__(128) __nv_bfloat16 g_xpT_lo[(size_t)NB * SPAD * CCH];
__device__ __align__(128) __nv_bfloat16 g_W1h[CCH * CCH], g_W1l[CCH * CCH];
__device__ __align__(128) __nv_bfloat16 g_Woh[CCH * CCH], g_Wol[CCH * CCH];
__device__ __align__(128) __nv_bfloat16 g_Wlwh[128 * CCH], g_Wlwl[128 * CCH];  // rows 96..127 stay 0
__device__ float g_blw[96];
__device__ __align__(128) float g_value[(size_t)NB * SSQ * CCH];   // (n,s,c) fp32
__device__ __align__(128) float g_offw [(size_t)NB * SSQ * 96];
__device__ __align__(128) __nv_bfloat16 g_smp_hi[(size_t)NB * SPAD * CCH];
__device__ __align__(128) __nv_bfloat16 g_smp_lo[(size_t)NB * SPAD * CCH];

// ---------------- PTX helpers (base sm_103 ISA only) ----------------
__device__ __forceinline__ uint32_t smem_u32(const void* p) {
    uint32_t a;
    asm("{ .reg .u64 t; cvta.to.shared.u64 t, %1; cvt.u32.u64 %0, t; }" : "=r"(a) : "l"(p));
    return a;
}
__device__ __forceinline__ void cpa16(uint32_t s, const void* g) {
    asm volatile("cp.async.cg.shared.global [%0], [%1], 16;" :: "r"(s), "l"(g));
}
#define CP_COMMIT() asm volatile("cp.async.commit_group;" ::: "memory")
#define CP_WAIT1()  asm volatile("cp.async.wait_group 1;" ::: "memory")
#define CP_WAIT0()  asm volatile("cp.async.wait_group 0;" ::: "memory")

#define LDSM4(r0, r1, r2, r3, adr) \
    asm volatile("ldmatrix.sync.aligned.m8n8.x4.shared.b16 {%0,%1,%2,%3}, [%4];" \
        : "=r"(r0), "=r"(r1), "=r"(r2), "=r"(r3) : "r"(adr))

#define MMA_BF16(d, a, b) \
    asm volatile("mma.sync.aligned.m16n8k16.row.col.f32.bf16.bf16.f32 " \
        "{%0,%1,%2,%3}, {%4,%5,%6,%7}, {%8,%9}, {%0,%1,%2,%3};" \
        : "+f"((d)[0]), "+f"((d)[1]), "+f"((d)[2]), "+f"((d)[3]) \
        : "r"((a)[0]), "r"((a)[1]), "r"((a)[2]), "r"((a)[3]), \
          "r"((b)[0]), "r"((b)[1]))

union Pack4 { __nv_bfloat162 b2[2]; uint2 u; };

// ---------------------------------------------------------------------------
// transpose + bf16 hi/lo convert: x(n,c,s) -> xT(n,s,c); (x+pos) likewise.
// Phase 2 packs 4 channels/thread -> coalesced 8B stores per array.
// ---------------------------------------------------------------------------
__global__ void __launch_bounds__(256) k_transpose(
    const float* __restrict__ x, const float* __restrict__ pos)
{
    __shared__ float tx_[32][33], tp_[32][33];
    const int n = blockIdx.z, c0 = blockIdx.y * 32, s0 = blockIdx.x * 32;
    const int t = threadIdx.x;
    const int ti = t & 31, tj = t >> 5;   // ti: s, tj: c-base
    const float* xb = x   + ((size_t)n * CCH + c0) * SSQ;
    const float* pb = pos + ((size_t)n * CCH + c0) * SSQ;
#pragma unroll
    for (int k = 0; k < 4; k++) {
        const int cl = tj + 8 * k, s = s0 + ti;
        float xv = 0.f, pv = 0.f;
        if (s < SSQ) { xv = xb[(size_t)cl * SSQ + s]; pv = pb[(size_t)cl * SSQ + s]; }
        tx_[cl][ti] = xv;
        tp_[cl][ti] = xv + pv;
    }
    __syncthreads();

    const int sl = t >> 3;           // 0..31
    const int cg = (t & 7) * 4;      // 0..28
    const int s  = s0 + sl;
    const bool ok = (s < SSQ);

    float xv[4], pv[4];
#pragma unroll
    for (int i = 0; i < 4; i++) {
        xv[i] = ok ? tx_[cg + i][sl] : 0.f;
        pv[i] = ok ? tp_[cg + i][sl] : 0.f;
    }
    Pack4 xh, xl, ph, pl;
#pragma unroll
    for (int i = 0; i < 2; i++) {
        __nv_bfloat16 h0 = __float2bfloat16(xv[2 * i]);
        __nv_bfloat16 h1 = __float2bfloat16(xv[2 * i + 1]);
        xh.b2[i] = __nv_bfloat162(h0, h1);
        xl.b2[i] = __nv_bfloat162(__float2bfloat16(xv[2 * i] - __bfloat162float(h0)),
                                  __float2bfloat16(xv[2 * i + 1] - __bfloat162float(h1)));
        h0 = __float2bfloat16(pv[2 * i]);
        h1 = __float2bfloat16(pv[2 * i + 1]);
        ph.b2[i] = __nv_bfloat162(h0, h1);
        pl.b2[i] = __nv_bfloat162(__float2bfloat16(pv[2 * i] - __bfloat162float(h0)),
                                  __float2bfloat16(pv[2 * i + 1] - __bfloat162float(h1)));
    }
    const size_t o = ((size_t)n * SPAD + s) * CCH + c0 + cg;
    *(uint2*)(g_xT_hi  + o) = xh.u;
    *(uint2*)(g_xT_lo  + o) = xl.u;
    *(uint2*)(g_xpT_hi + o) = ph.u;
    *(uint2*)(g_xpT_lo + o) = pl.u;
}

// ---------------------------------------------------------------------------
// weight convert
// ---------------------------------------------------------------------------
__global__ void __launch_bounds__(256) k_wconv(
    const float* __restrict__ Wv, const float* __restrict__ Wo,
    const float* __restrict__ Wloc, const float* __restrict__ Ww,
    const float* __restrict__ bloc, const float* __restrict__ bw)
{
    const int i = blockIdx.x * 256 + threadIdx.x;
    if (i < CCH * CCH) {
        float v = Wv[i];
        __nv_bfloat16 h = __float2bfloat16(v);
        g_W1h[i] = h; g_W1l[i] = __float2bfloat16(v - __bfloat162float(h));
        v = Wo[i];
        h = __float2bfloat16(v);
        g_Woh[i] = h; g_Wol[i] = __float2bfloat16(v - __bfloat162float(h));
    }
    if (i < 96 * CCH) {
        const int r = i >> 9, c = i & 511;
        const float v = (r < 64) ? Wloc[r * 512 + c] : Ww[(r - 64) * 512 + c];
        __nv_bfloat16 h = __float2bfloat16(v);
        g_Wlwh[i] = h; g_Wlwl[i] = __float2bfloat16(v - __bfloat162float(h));
    }
    if (i < 96) g_blw[i] = (i < 64) ? bloc[i] : bw[i - 64];
}

// ---------------------------------------------------------------------------
// bf16x3 HMMA mainloop (unchanged from R6)
// ---------------------------------------------------------------------------
__device__ __forceinline__ void hmma_mainloop(
    uint32_t smem,
    const __nv_bfloat16* __restrict__ Ah, const __nv_bfloat16* __restrict__ Al,
    const __nv_bfloat16* __restrict__ Bh, const __nv_bfloat16* __restrict__ Bl,
    float acc[2][8][4])
{
    const int t = threadIdx.x;
    const int lane = t & 31, wid = t >> 5;
    const int wm = (wid & 3) * 32, wn = (wid >> 2) * 64;

    auto issue = [&](int st, int c0) {
        const uint32_t sb = smem + st * STG;
#pragma unroll
        for (int r = 0; r < 2; r++) {
            const int id  = t + 256 * r;
            const int row = id >> 2;
            const int kc  = id & 3;
            const uint32_t so = row * ROWB + kc * 16;
            const size_t go = (size_t)row * CCH + c0 + kc * 8;
            cpa16(sb + 0 * ASZ + so, Ah + go);
            cpa16(sb + 1 * ASZ + so, Al + go);
            cpa16(sb + 2 * ASZ + so, Bh + go);
            cpa16(sb + 3 * ASZ + so, Bl + go);
        }
    };

    issue(0, 0);
    CP_COMMIT();

#pragma unroll 1
    for (int ch = 0; ch < NCH; ch++) {
        if (ch + 1 < NCH) {
            issue((ch + 1) & 1, (ch + 1) * KCH);
            CP_COMMIT();
            CP_WAIT1();
        } else {
            CP_WAIT0();
        }
        __syncthreads();

        const uint32_t sb = smem + (ch & 1) * STG;
        const uint32_t sAh = sb, sAl = sb + ASZ, sBh = sb + 2 * ASZ, sBl = sb + 3 * ASZ;

#pragma unroll
        for (int ks = 0; ks < 2; ks++) {
            const int k16 = ks * 16;
            uint32_t ah[2][4], al[2][4], bh[8][2], bl[8][2];

            const uint32_t aoff = (wm + (lane & 15)) * ROWB +
                                  (k16 + ((lane >> 4) << 3)) * 2;
#pragma unroll
            for (int m = 0; m < 2; m++) {
                const uint32_t ao = aoff + m * 16 * ROWB;
                LDSM4(ah[m][0], ah[m][1], ah[m][2], ah[m][3], sAh + ao);
                LDSM4(al[m][0], al[m][1], al[m][2], al[m][3], sAl + ao);
            }
            const uint32_t brow = (lane & 7) + ((lane & 16) >> 1);
            const uint32_t bcol = (k16 + (((lane >> 3) & 1) << 3)) * 2;
#pragma unroll
            for (int p = 0; p < 4; p++) {
                const uint32_t bo = (wn + p * 16 + brow) * ROWB + bcol;
                LDSM4(bh[2 * p][0], bh[2 * p][1], bh[2 * p + 1][0], bh[2 * p + 1][1], sBh + bo);
                LDSM4(bl[2 * p][0], bl[2 * p][1], bl[2 * p + 1][0], bl[2 * p + 1][1], sBl + bo);
            }

#pragma unroll
            for (int m = 0; m < 2; m++)
#pragma unroll
                for (int ni = 0; ni < 8; ni++) MMA_BF16(acc[m][ni], ah[m], bh[ni]);
#pragma unroll
            for (int m = 0; m < 2; m++)
#pragma unroll
                for (int ni = 0; ni < 8; ni++) MMA_BF16(acc[m][ni], ah[m], bl[ni]);
#pragma unroll
            for (int m = 0; m < 2; m++)
#pragma unroll
                for (int ni = 0; ni < 8; ni++) MMA_BF16(acc[m][ni], al[m], bh[ni]);
        }
        __syncthreads();
    }
}

// ---------------------------------------------------------------------------
// GEMM kernel 1: y<4 -> value tile, y==4 -> locw
// ---------------------------------------------------------------------------
__global__ void __launch_bounds__(256) k_mma1(const float* __restrict__ bv)
{
    extern __shared__ char smc[];
    const uint32_t smem = smem_u32(smc);
    const int t = threadIdx.x, lane = t & 31, wid = t >> 5;
    const int wm = (wid & 3) * 32, wn = (wid >> 2) * 64;
    const int n = blockIdx.z, yt = blockIdx.y, s0 = blockIdx.x * 128;

    float acc[2][8][4];
#pragma unroll
    for (int m = 0; m < 2; m++)
#pragma unroll
        for (int ni = 0; ni < 8; ni++)
#pragma unroll
            for (int j = 0; j < 4; j++) acc[m][ni][j] = 0.f;

    const size_t aoff = ((size_t)n * SPAD + s0) * CCH;
    if (yt < 4) {
        hmma_mainloop(smem, g_xT_hi + aoff, g_xT_lo + aoff,
                      g_W1h + (size_t)yt * 128 * CCH, g_W1l + (size_t)yt * 128 * CCH, acc);
        const int o0 = yt * 128;
#pragma unroll
        for (int m = 0; m < 2; m++) {
            const int r0 = s0 + wm + m * 16 + (lane >> 2);
            const int r1 = r0 + 8;
#pragma unroll
            for (int ni = 0; ni < 8; ni++) {
                const int col = o0 + wn + ni * 8 + (lane & 3) * 2;
                const float b0 = bv[col], b1 = bv[col + 1];
                if (r0 < SSQ) {
                    float2 v = make_float2(acc[m][ni][0] + b0, acc[m][ni][1] + b1);
                    *(float2*)(g_value + ((size_t)n * SSQ + r0) * CCH + col) = v;
                }
                if (r1 < SSQ) {
                    float2 v = make_float2(acc[m][ni][2] + b0, acc[m][ni][3] + b1);
                    *(float2*)(g_value + ((size_t)n * SSQ + r1) * CCH + col) = v;
                }
            }
        }
    } else {
        hmma_mainloop(smem, g_xpT_hi + aoff, g_xpT_lo + aoff, g_Wlwh, g_Wlwl, acc);
#pragma unroll
        for (int m = 0; m < 2; m++) {
            const int r0 = s0 + wm + m * 16 + (lane >> 2);
            const int r1 = r0 + 8;
#pragma unroll
            for (int ni = 0; ni < 8; ni++) {
                const int col = wn + ni * 8 + (lane & 3) * 2;
                if (col >= 96) continue;
                const float b0 = g_blw[col], b1 = g_blw[col + 1];
                if (r0 < SSQ) {
                    float2 v = make_float2(acc[m][ni][0] + b0, acc[m][ni][1] + b1);
                    *(float2*)(g_offw + ((size_t)n * SSQ + r0) * 96 + col) = v;
                }
                if (r1 < SSQ) {
                    float2 v = make_float2(acc[m][ni][2] + b0, acc[m][ni][3] + b1);
                    *(float2*)(g_offw + ((size_t)n * SSQ + r1) * 96 + col) = v;
                }
            }
        }
    }
}

// ---------------------------------------------------------------------------
// GEMM kernel 2: out[n, o, s] = (samp[s,:]·Wo[o,:] + bo[o]) * scale[o]
// ---------------------------------------------------------------------------
__global__ void __launch_bounds__(256) k_mma2(
    const float* __restrict__ bo, const float* __restrict__ scale,
    float* __restrict__ out)
{
    extern __shared__ char smc[];
    const uint32_t smem = smem_u32(smc);
    const int t = threadIdx.x, lane = t & 31, wid = t >> 5;
    const int wm = (wid & 3) * 32, wn = (wid >> 2) * 64;
    const int n = blockIdx.z, s0 = blockIdx.x * 128, o0 = blockIdx.y * 128;

    float acc[2][8][4];
#pragma unroll
    for (int m = 0; m < 2; m++)
#pragma unroll
        for (int ni = 0; ni < 8; ni++)
#pragma unroll
            for (int j = 0; j < 4; j++) acc[m][ni][j] = 0.f;

    const size_t aoff = ((size_t)n * SPAD + s0) * CCH;
    hmma_mainloop(smem, g_smp_hi + aoff, g_smp_lo + aoff,
                  g_Woh + (size_t)o0 * CCH, g_Wol + (size_t)o0 * CCH, acc);

    __syncthreads();
    float* ss = (float*)smc;
#pragma unroll
    for (int m = 0; m < 2; m++) {
        const int r0 = wm + m * 16 + (lane >> 2);
#pragma unroll
        for (int ni = 0; ni < 8; ni++) {
            const int col = wn + ni * 8 + (lane & 3) * 2;
            ss[r0 * 132 + col]           = acc[m][ni][0];
            ss[r0 * 132 + col + 1]       = acc[m][ni][1];
            ss[(r0 + 8) * 132 + col]     = acc[m][ni][2];
            ss[(r0 + 8) * 132 + col + 1] = acc[m][ni][3];
        }
    }
    __syncthreads();

    const int o  = t & 127;
    const int sh = (t >> 7) * 64;
    const float bb = bo[o0 + o], sc = scale[o0 + o];
    float* dst = out + ((size_t)n * CCH + o0 + o) * SSQ;
#pragma unroll
    for (int j = 0; j < 32; j++) {
        const int s = sh + j * 2, gs = s0 + s;
        const float v0 = (ss[s * 132 + o] + bb) * sc;
        const float v1 = (ss[(s + 1) * 132 + o] + bb) * sc;
        if (gs + 1 < SSQ) {
            *(float2*)(dst + gs) = make_float2(v0, v1);
        } else {
            if (gs < SSQ) dst[gs] = v0;
        }
    }
}

// ---------------------------------------------------------------------------
// Sampling: one warp per (n, q, m). Lane covers channels m*64 + 2*lane{,+1}.
// Branchless clamped corners (matches reference's clip+mask gather).
// ---------------------------------------------------------------------------
__global__ void __launch_bounds__(256) k_sample(
    const float* __restrict__ valid_sizes, const float* __restrict__ valid_scales)
{
    const int warp = (blockIdx.x * blockDim.x + threadIdx.x) >> 5;
    const int lane = threadIdx.x & 31;
    if (warp >= NB * SSQ * MM) return;

    const int m = warp & (MM - 1);
    const int q = (warp >> 3) % SSQ;
    const int n = warp / (SSQ * MM);

    const int lvl = (q < 10000) ? 0 : (q < 12500) ? 1 : (q < 13125) ? 2 : 3;
    const int Wl  = c_lvl_w[lvl];
    const int lq  = q - c_lvl_off[lvl];
    const float qxc = (float)(lq % Wl) + 0.5f;
    const float qyc = (float)(lq / Wl) + 0.5f;

    const float* row = g_offw + ((size_t)n * SSQ + q) * 96;

    float lg[4];
#pragma unroll
    for (int f = 0; f < 4; f++) lg[f] = row[64 + m * 4 + f];
    float mx = fmaxf(fmaxf(lg[0], lg[1]), fmaxf(lg[2], lg[3]));
    float e[4], ssum = 0.f;
#pragma unroll
    for (int f = 0; f < 4; f++) { e[f] = expf(lg[f] - mx); ssum += e[f]; }
    const float inv = 1.f / ssum;

    const float vsx = valid_sizes[(n * FLV + lvl) * 2 + 0];
    const float vsy = valid_sizes[(n * FLV + lvl) * 2 + 1];

    float accx = 0.f, accy = 0.f;
    // float2 view: row stride = 256 float2; lane channel pair = m*32 + lane
    const float2* vbase = (const float2*)g_value + (size_t)n * SSQ * 256 + m * 32 + lane;

#pragma unroll
    for (int f = 0; f < 4; f++) {
        const float wf  = e[f] * inv;
        const float scx = 2.f * valid_scales[(n * FLV + f) * 2 + 0] / vsx;
        const float scy = 2.f * valid_scales[(n * FLV + f) * 2 + 1] / vsy;
        const float ox  = row[(m * 4 + f) * 2 + 0];
        const float oy  = row[(m * 4 + f) * 2 + 1];
        const float gx  = (ox + qxc) * scx - 1.f;
        const float gy  = (oy + qyc) * scy - 1.f;

        const int Wf = c_lvl_w[f];
        const float px = (gx + 1.f) * (Wf * 0.5f) - 0.5f;
        const float py = (gy + 1.f) * (Wf * 0.5f) - 0.5f;
        const float x0f = floorf(px), y0f = floorf(py);
        const int   x0 = (int)x0f,   y0 = (int)y0f;
        const int   x1 = x0 + 1,     y1 = y0 + 1;
        const float wx1 = px - x0f,  wy1 = py - y0f;

        // validity-masked weights + clamped indices (== reference clip+mask)
        const float vx0 = (x0 >= 0 && x0 < Wf) ? (1.f - wx1) : 0.f;
        const float vx1 = (x1 >= 0 && x1 < Wf) ? wx1 : 0.f;
        const float vy0 = (y0 >= 0 && y0 < Wf) ? (1.f - wy1) : 0.f;
        const float vy1 = (y1 >= 0 && y1 < Wf) ? wy1 : 0.f;
        const int xc0 = min(max(x0, 0), Wf - 1);
        const int xc1 = min(max(x1, 0), Wf - 1);
        const int yc0 = min(max(y0, 0), Wf - 1);
        const int yc1 = min(max(y1, 0), Wf - 1);

        const int r0 = c_lvl_off[f] + yc0 * Wf;
        const int r1 = c_lvl_off[f] + yc1 * Wf;

        const float w00 = wf * vy0 * vx0;
        const float w01 = wf * vy0 * vx1;
        const float w10 = wf * vy1 * vx0;
        const float w11 = wf * vy1 * vx1;

        const float2 v00 = vbase[(r0 + xc0) * 256];
        const float2 v01 = vbase[(r0 + xc1) * 256];
        const float2 v10 = vbase[(r1 + xc0) * 256];
        const float2 v11 = vbase[(r1 + xc1) * 256];

        accx = fmaf(w00, v00.x, accx); accy = fmaf(w00, v00.y, accy);
        accx = fmaf(w01, v01.x, accx); accy = fmaf(w01, v01.y, accy);
        accx = fmaf(w10, v10.x, accx); accy = fmaf(w10, v10.y, accy);
        accx = fmaf(w11, v11.x, accx); accy = fmaf(w11, v11.y, accy);
    }

    const size_t ob = ((size_t)n * SPAD + q) * CCH + m * 64 + 2 * lane;
    __nv_bfloat16 h0 = __float2bfloat16(accx);
    __nv_bfloat16 h1 = __float2bfloat16(accy);
    *(__nv_bfloat162*)(g_smp_hi + ob) = __nv_bfloat162(h0, h1);
    *(__nv_bfloat162*)(g_smp_lo + ob) = __nv_bfloat162(
        __float2bfloat16(accx - __bfloat162float(h0)),
        __float2bfloat16(accy - __bfloat162float(h1)));
}

// ---------------------------------------------------------------------------
extern "C" void kernel_launch(void* const* d_in, const int* in_sizes, int n_in,
                              void* d_out, int out_size)
{
    const float* x            = (const float*)d_in[0];
    const float* pos          = (const float*)d_in[1];
    const float* valid_sizes  = (const float*)d_in[3];
    const float* valid_scales = (const float*)d_in[4];
    const float* Wv           = (const float*)d_in[5];
    const float* bv           = (const float*)d_in[6];
    const float* Wloc         = (const float*)d_in[7];
    const float* bloc         = (const float*)d_in[8];
    const float* Ww           = (const float*)d_in[9];
    const float* bw           = (const float*)d_in[10];
    const float* Wo           = (const float*)d_in[11];
    const float* bo           = (const float*)d_in[12];
    const float* scale        = (const float*)d_in[13];
    float* out = (float*)d_out;

    static bool attr_set = false;
    if (!attr_set) {
        cudaFuncSetAttribute(k_mma1, cudaFuncAttributeMaxDynamicSharedMemorySize, SMEM_SZ);
        cudaFuncSetAttribute(k_mma2, cudaFuncAttributeMaxDynamicSharedMemorySize, SMEM_SZ);
        attr_set = true;
    }

    dim3 gt(SPAD / 32, CCH / 32, NB);
    k_transpose<<<gt, 256>>>(x, pos);

    k_wconv<<<(CCH * CCH) / 256, 256>>>(Wv, Wo, Wloc, Ww, bloc, bw);

    dim3 g1(SPAD / 128, 5, NB);
    k_mma1<<<g1, 256, SMEM_SZ>>>(bv);

    const int nwarps = NB * SSQ * MM;
    k_sample<<<(nwarps * 32 + 255) / 256, 256>>>(valid_sizes, valid_scales);

    dim3 g2(SPAD / 128, CCH / 128, NB);
    k_mma2<<<g2, 256, SMEM_SZ>>>(bo, scale, out);
}

// round 11
// speedup vs baseline: 1.9873x; 1.0035x over previous
#include <cuda_runtime.h>
#include <cuda_bf16.h>
#include <cstdint>

#define NB   2
#define CCH  512
#define MM   8
#define FLV  4
#define SSQ  13294
#define SPAD 13312            // 104*128
#define KCH  32               // K per chunk (bf16)
#define NCH  (CCH/KCH)        // 16
#define ROWB 80               // padded smem row stride bytes (40 bf16), 16B-aligned rows
#define ASZ  (128*ROWB)       // 10240 B per operand array
#define STG  (4*ASZ)          // 40960 B per stage {Ah,Al,Bh,Bl}
#define SMEM_SZ (2*STG)       // 81920 (also covers 128x132 f32 epilogue = 67584)

__constant__ int c_lvl_off[4] = {0, 10000, 12500, 13125};
__constant__ int c_lvl_w[4]   = {100, 50, 25, 13};

// ---------------- device scratch ----------------
__device__ __align__(128) __nv_bfloat16 g_xT_hi [(size_t)NB * SPAD * CCH];
__device__ __align__(128) __nv_bfloat16 g_xT_lo [(size_t)NB * SPAD * CCH];
__device__ __align__(128) __nv_bfloat16 g_xpT_hi[(size_t)NB * SPAD * CCH];
__device__ __align__(128) __nv_bfloat16 g_xpT_lo[(size_t)NB * SPAD * CCH];
__device__ __align__(128) __nv_bfloat16 g_W1h[CCH * CCH], g_W1l[CCH * CCH];
__device__ __align__(128) __nv_bfloat16 g_Woh[CCH * CCH], g_Wol[CCH * CCH];
__device__ __align__(128) __nv_bfloat16 g_Wlwh[128 * CCH], g_Wlwl[128 * CCH];  // rows 96..127 stay 0
__device__ float g_blw[96];
__device__ __align__(128) float g_value[(size_t)NB * SSQ * CCH];   // (n,s,c) fp32
__device__ __align__(128) float g_offw [(size_t)NB * SSQ * 96];
__device__ __align__(128) __nv_bfloat16 g_smp_hi[(size_t)NB * SPAD * CCH];
__device__ __align__(128) __nv_bfloat16 g_smp_lo[(size_t)NB * SPAD * CCH];

// ---------------- PTX helpers (base sm_103 ISA only) ----------------
__device__ __forceinline__ uint32_t smem_u32(const void* p) {
    uint32_t a;
    asm("{ .reg .u64 t; cvta.to.shared.u64 t, %1; cvt.u32.u64 %0, t; }" : "=r"(a) : "l"(p));
    return a;
}
__device__ __forceinline__ void cpa16(uint32_t s, const void* g) {
    asm volatile("cp.async.cg.shared.global [%0], [%1], 16;" :: "r"(s), "l"(g));
}
#define CP_COMMIT() asm volatile("cp.async.commit_group;" ::: "memory")
#define CP_WAIT1()  asm volatile("cp.async.wait_group 1;" ::: "memory")
#define CP_WAIT0()  asm volatile("cp.async.wait_group 0;" ::: "memory")

#define LDSM4(r0, r1, r2, r3, adr) \
    asm volatile("ldmatrix.sync.aligned.m8n8.x4.shared.b16 {%0,%1,%2,%3}, [%4];" \
        : "=r"(r0), "=r"(r1), "=r"(r2), "=r"(r3) : "r"(adr))

#define MMA_BF16(d, a, b) \
    asm volatile("mma.sync.aligned.m16n8k16.row.col.f32.bf16.bf16.f32 " \
        "{%0,%1,%2,%3}, {%4,%5,%6,%7}, {%8,%9}, {%0,%1,%2,%3};" \
        : "+f"((d)[0]), "+f"((d)[1]), "+f"((d)[2]), "+f"((d)[3]) \
        : "r"((a)[0]), "r"((a)[1]), "r"((a)[2]), "r"((a)[3]), \
          "r"((b)[0]), "r"((b)[1]))

union Pack4 { __nv_bfloat162 b2[2]; uint2 u; };

// ---------------------------------------------------------------------------
// transpose + bf16 hi/lo convert: x(n,c,s) -> xT(n,s,c); (x+pos) likewise.
// Phase 2 packs 4 channels/thread -> coalesced 8B stores per array.
// ---------------------------------------------------------------------------
__global__ void __launch_bounds__(256) k_transpose(
    const float* __restrict__ x, const float* __restrict__ pos)
{
    __shared__ float tx_[32][33], tp_[32][33];
    const int n = blockIdx.z, c0 = blockIdx.y * 32, s0 = blockIdx.x * 32;
    const int t = threadIdx.x;
    const int ti = t & 31, tj = t >> 5;   // ti: s, tj: c-base
    const float* xb = x   + ((size_t)n * CCH + c0) * SSQ;
    const float* pb = pos + ((size_t)n * CCH + c0) * SSQ;
#pragma unroll
    for (int k = 0; k < 4; k++) {
        const int cl = tj + 8 * k, s = s0 + ti;
        float xv = 0.f, pv = 0.f;
        if (s < SSQ) { xv = xb[(size_t)cl * SSQ + s]; pv = pb[(size_t)cl * SSQ + s]; }
        tx_[cl][ti] = xv;
        tp_[cl][ti] = xv + pv;
    }
    __syncthreads();

    const int sl = t >> 3;           // 0..31
    const int cg = (t & 7) * 4;      // 0..28
    const int s  = s0 + sl;
    const bool ok = (s < SSQ);

    float xv[4], pv[4];
#pragma unroll
    for (int i = 0; i < 4; i++) {
        xv[i] = ok ? tx_[cg + i][sl] : 0.f;
        pv[i] = ok ? tp_[cg + i][sl] : 0.f;
    }
    Pack4 xh, xl, ph, pl;
#pragma unroll
    for (int i = 0; i < 2; i++) {
        __nv_bfloat16 h0 = __float2bfloat16(xv[2 * i]);
        __nv_bfloat16 h1 = __float2bfloat16(xv[2 * i + 1]);
        xh.b2[i] = __nv_bfloat162(h0, h1);
        xl.b2[i] = __nv_bfloat162(__float2bfloat16(xv[2 * i] - __bfloat162float(h0)),
                                  __float2bfloat16(xv[2 * i + 1] - __bfloat162float(h1)));
        h0 = __float2bfloat16(pv[2 * i]);
        h1 = __float2bfloat16(pv[2 * i + 1]);
        ph.b2[i] = __nv_bfloat162(h0, h1);
        pl.b2[i] = __nv_bfloat162(__float2bfloat16(pv[2 * i] - __bfloat162float(h0)),
                                  __float2bfloat16(pv[2 * i + 1] - __bfloat162float(h1)));
    }
    const size_t o = ((size_t)n * SPAD + s) * CCH + c0 + cg;
    *(uint2*)(g_xT_hi  + o) = xh.u;
    *(uint2*)(g_xT_lo  + o) = xl.u;
    *(uint2*)(g_xpT_hi + o) = ph.u;
    *(uint2*)(g_xpT_lo + o) = pl.u;
}

// ---------------------------------------------------------------------------
// weight convert
// ---------------------------------------------------------------------------
__global__ void __launch_bounds__(256) k_wconv(
    const float* __restrict__ Wv, const float* __restrict__ Wo,
    const float* __restrict__ Wloc, const float* __restrict__ Ww,
    const float* __restrict__ bloc, const float* __restrict__ bw)
{
    const int i = blockIdx.x * 256 + threadIdx.x;
    if (i < CCH * CCH) {
        float v = Wv[i];
        __nv_bfloat16 h = __float2bfloat16(v);
        g_W1h[i] = h; g_W1l[i] = __float2bfloat16(v - __bfloat162float(h));
        v = Wo[i];
        h = __float2bfloat16(v);
        g_Woh[i] = h; g_Wol[i] = __float2bfloat16(v - __bfloat162float(h));
    }
    if (i < 96 * CCH) {
        const int r = i >> 9, c = i & 511;
        const float v = (r < 64) ? Wloc[r * 512 + c] : Ww[(r - 64) * 512 + c];
        __nv_bfloat16 h = __float2bfloat16(v);
        g_Wlwh[i] = h; g_Wlwl[i] = __float2bfloat16(v - __bfloat162float(h));
    }
    if (i < 96) g_blw[i] = (i < 64) ? bloc[i] : bw[i - 64];
}

// ---------------------------------------------------------------------------
// bf16x3 HMMA mainloop (unchanged from R6)
// ---------------------------------------------------------------------------
__device__ __forceinline__ void hmma_mainloop(
    uint32_t smem,
    const __nv_bfloat16* __restrict__ Ah, const __nv_bfloat16* __restrict__ Al,
    const __nv_bfloat16* __restrict__ Bh, const __nv_bfloat16* __restrict__ Bl,
    float acc[2][8][4])
{
    const int t = threadIdx.x;
    const int lane = t & 31, wid = t >> 5;
    const int wm = (wid & 3) * 32, wn = (wid >> 2) * 64;

    auto issue = [&](int st, int c0) {
        const uint32_t sb = smem + st * STG;
#pragma unroll
        for (int r = 0; r < 2; r++) {
            const int id  = t + 256 * r;
            const int row = id >> 2;
            const int kc  = id & 3;
            const uint32_t so = row * ROWB + kc * 16;
            const size_t go = (size_t)row * CCH + c0 + kc * 8;
            cpa16(sb + 0 * ASZ + so, Ah + go);
            cpa16(sb + 1 * ASZ + so, Al + go);
            cpa16(sb + 2 * ASZ + so, Bh + go);
            cpa16(sb + 3 * ASZ + so, Bl + go);
        }
    };

    issue(0, 0);
    CP_COMMIT();

#pragma unroll 1
    for (int ch = 0; ch < NCH; ch++) {
        if (ch + 1 < NCH) {
            issue((ch + 1) & 1, (ch + 1) * KCH);
            CP_COMMIT();
            CP_WAIT1();
        } else {
            CP_WAIT0();
        }
        __syncthreads();

        const uint32_t sb = smem + (ch & 1) * STG;
        const uint32_t sAh = sb, sAl = sb + ASZ, sBh = sb + 2 * ASZ, sBl = sb + 3 * ASZ;

#pragma unroll
        for (int ks = 0; ks < 2; ks++) {
            const int k16 = ks * 16;
            uint32_t ah[2][4], al[2][4], bh[8][2], bl[8][2];

            const uint32_t aoff = (wm + (lane & 15)) * ROWB +
                                  (k16 + ((lane >> 4) << 3)) * 2;
#pragma unroll
            for (int m = 0; m < 2; m++) {
                const uint32_t ao = aoff + m * 16 * ROWB;
                LDSM4(ah[m][0], ah[m][1], ah[m][2], ah[m][3], sAh + ao);
                LDSM4(al[m][0], al[m][1], al[m][2], al[m][3], sAl + ao);
            }
            const uint32_t brow = (lane & 7) + ((lane & 16) >> 1);
            const uint32_t bcol = (k16 + (((lane >> 3) & 1) << 3)) * 2;
#pragma unroll
            for (int p = 0; p < 4; p++) {
                const uint32_t bo = (wn + p * 16 + brow) * ROWB + bcol;
                LDSM4(bh[2 * p][0], bh[2 * p][1], bh[2 * p + 1][0], bh[2 * p + 1][1], sBh + bo);
                LDSM4(bl[2 * p][0], bl[2 * p][1], bl[2 * p + 1][0], bl[2 * p + 1][1], sBl + bo);
            }

#pragma unroll
            for (int m = 0; m < 2; m++)
#pragma unroll
                for (int ni = 0; ni < 8; ni++) MMA_BF16(acc[m][ni], ah[m], bh[ni]);
#pragma unroll
            for (int m = 0; m < 2; m++)
#pragma unroll
                for (int ni = 0; ni < 8; ni++) MMA_BF16(acc[m][ni], ah[m], bl[ni]);
#pragma unroll
            for (int m = 0; m < 2; m++)
#pragma unroll
                for (int ni = 0; ni < 8; ni++) MMA_BF16(acc[m][ni], al[m], bh[ni]);
        }
        __syncthreads();
    }
}

// ---------------------------------------------------------------------------
// GEMM kernel 1: y<4 -> value tile, y==4 -> locw
// ---------------------------------------------------------------------------
__global__ void __launch_bounds__(256) k_mma1(const float* __restrict__ bv)
{
    extern __shared__ char smc[];
    const uint32_t smem = smem_u32(smc);
    const int t = threadIdx.x, lane = t & 31, wid = t >> 5;
    const int wm = (wid & 3) * 32, wn = (wid >> 2) * 64;
    const int n = blockIdx.z, yt = blockIdx.y, s0 = blockIdx.x * 128;

    float acc[2][8][4];
#pragma unroll
    for (int m = 0; m < 2; m++)
#pragma unroll
        for (int ni = 0; ni < 8; ni++)
#pragma unroll
            for (int j = 0; j < 4; j++) acc[m][ni][j] = 0.f;

    const size_t aoff = ((size_t)n * SPAD + s0) * CCH;
    if (yt < 4) {
        hmma_mainloop(smem, g_xT_hi + aoff, g_xT_lo + aoff,
                      g_W1h + (size_t)yt * 128 * CCH, g_W1l + (size_t)yt * 128 * CCH, acc);
        const int o0 = yt * 128;
#pragma unroll
        for (int m = 0; m < 2; m++) {
            const int r0 = s0 + wm + m * 16 + (lane >> 2);
            const int r1 = r0 + 8;
#pragma unroll
            for (int ni = 0; ni < 8; ni++) {
                const int col = o0 + wn + ni * 8 + (lane & 3) * 2;
                const float b0 = bv[col], b1 = bv[col + 1];
                if (r0 < SSQ) {
                    float2 v = make_float2(acc[m][ni][0] + b0, acc[m][ni][1] + b1);
                    *(float2*)(g_value + ((size_t)n * SSQ + r0) * CCH + col) = v;
                }
                if (r1 < SSQ) {
                    float2 v = make_float2(acc[m][ni][2] + b0, acc[m][ni][3] + b1);
                    *(float2*)(g_value + ((size_t)n * SSQ + r1) * CCH + col) = v;
                }
            }
        }
    } else {
        hmma_mainloop(smem, g_xpT_hi + aoff, g_xpT_lo + aoff, g_Wlwh, g_Wlwl, acc);
#pragma unroll
        for (int m = 0; m < 2; m++) {
            const int r0 = s0 + wm + m * 16 + (lane >> 2);
            const int r1 = r0 + 8;
#pragma unroll
            for (int ni = 0; ni < 8; ni++) {
                const int col = wn + ni * 8 + (lane & 3) * 2;
                if (col >= 96) continue;
                const float b0 = g_blw[col], b1 = g_blw[col + 1];
                if (r0 < SSQ) {
                    float2 v = make_float2(acc[m][ni][0] + b0, acc[m][ni][1] + b1);
                    *(float2*)(g_offw + ((size_t)n * SSQ + r0) * 96 + col) = v;
                }
                if (r1 < SSQ) {
                    float2 v = make_float2(acc[m][ni][2] + b0, acc[m][ni][3] + b1);
                    *(float2*)(g_offw + ((size_t)n * SSQ + r1) * 96 + col) = v;
                }
            }
        }
    }
}

// ---------------------------------------------------------------------------
// GEMM kernel 2: out[n, o, s] = (samp[s,:]·Wo[o,:] + bo[o]) * scale[o]
// ---------------------------------------------------------------------------
__global__ void __launch_bounds__(256) k_mma2(
    const float* __restrict__ bo, const float* __restrict__ scale,
    float* __restrict__ out)
{
    extern __shared__ char smc[];
    const uint32_t smem = smem_u32(smc);
    const int t = threadIdx.x, lane = t & 31, wid = t >> 5;
    const int wm = (wid & 3) * 32, wn = (wid >> 2) * 64;
    const int n = blockIdx.z, s0 = blockIdx.x * 128, o0 = blockIdx.y * 128;

    float acc[2][8][4];
#pragma unroll
    for (int m = 0; m < 2; m++)
#pragma unroll
        for (int ni = 0; ni < 8; ni++)
#pragma unroll
            for (int j = 0; j < 4; j++) acc[m][ni][j] = 0.f;

    const size_t aoff = ((size_t)n * SPAD + s0) * CCH;
    hmma_mainloop(smem, g_smp_hi + aoff, g_smp_lo + aoff,
                  g_Woh + (size_t)o0 * CCH, g_Wol + (size_t)o0 * CCH, acc);

    __syncthreads();
    float* ss = (float*)smc;
#pragma unroll
    for (int m = 0; m < 2; m++) {
        const int r0 = wm + m * 16 + (lane >> 2);
#pragma unroll
        for (int ni = 0; ni < 8; ni++) {
            const int col = wn + ni * 8 + (lane & 3) * 2;
            ss[r0 * 132 + col]           = acc[m][ni][0];
            ss[r0 * 132 + col + 1]       = acc[m][ni][1];
            ss[(r0 + 8) * 132 + col]     = acc[m][ni][2];
            ss[(r0 + 8) * 132 + col + 1] = acc[m][ni][3];
        }
    }
    __syncthreads();

    const int o  = t & 127;
    const int sh = (t >> 7) * 64;
    const float bb = bo[o0 + o], sc = scale[o0 + o];
    float* dst = out + ((size_t)n * CCH + o0 + o) * SSQ;
#pragma unroll
    for (int j = 0; j < 32; j++) {
        const int s = sh + j * 2, gs = s0 + s;
        const float v0 = (ss[s * 132 + o] + bb) * sc;
        const float v1 = (ss[(s + 1) * 132 + o] + bb) * sc;
        if (gs + 1 < SSQ) {
            *(float2*)(dst + gs) = make_float2(v0, v1);
        } else {
            if (gs < SSQ) dst[gs] = v0;
        }
    }
}

// ---------------------------------------------------------------------------
// Sampling: one warp per (n, q, m). Lane covers channels m*64 + 2*lane{,+1}.
// Branchless clamped corners (matches reference's clip+mask gather).
// ---------------------------------------------------------------------------
__global__ void __launch_bounds__(256) k_sample(
    const float* __restrict__ valid_sizes, const float* __restrict__ valid_scales)
{
    const int warp = (blockIdx.x * blockDim.x + threadIdx.x) >> 5;
    const int lane = threadIdx.x & 31;
    if (warp >= NB * SSQ * MM) return;

    const int m = warp & (MM - 1);
    const int q = (warp >> 3) % SSQ;
    const int n = warp / (SSQ * MM);

    const int lvl = (q < 10000) ? 0 : (q < 12500) ? 1 : (q < 13125) ? 2 : 3;
    const int Wl  = c_lvl_w[lvl];
    const int lq  = q - c_lvl_off[lvl];
    const float qxc = (float)(lq % Wl) + 0.5f;
    const float qyc = (float)(lq / Wl) + 0.5f;

    const float* row = g_offw + ((size_t)n * SSQ + q) * 96;

    float lg[4];
#pragma unroll
    for (int f = 0; f < 4; f++) lg[f] = row[64 + m * 4 + f];
    float mx = fmaxf(fmaxf(lg[0], lg[1]), fmaxf(lg[2], lg[3]));
    float e[4], ssum = 0.f;
#pragma unroll
    for (int f = 0; f < 4; f++) { e[f] = expf(lg[f] - mx); ssum += e[f]; }
    const float inv = 1.f / ssum;

    const float vsx = valid_sizes[(n * FLV + lvl) * 2 + 0];
    const float vsy = valid_sizes[(n * FLV + lvl) * 2 + 1];

    float accx = 0.f, accy = 0.f;
    // float2 view: row stride = 256 float2; lane channel pair = m*32 + lane
    const float2* vbase = (const float2*)g_value + (size_t)n * SSQ * 256 + m * 32 + lane;

#pragma unroll
    for (int f = 0; f < 4; f++) {
        const float wf  = e[f] * inv;
        const float scx = 2.f * valid_scales[(n * FLV + f) * 2 + 0] / vsx;
        const float scy = 2.f * valid_scales[(n * FLV + f) * 2 + 1] / vsy;
        const float ox  = row[(m * 4 + f) * 2 + 0];
        const float oy  = row[(m * 4 + f) * 2 + 1];
        const float gx  = (ox + qxc) * scx - 1.f;
        const float gy  = (oy + qyc) * scy - 1.f;

        const int Wf = c_lvl_w[f];
        const float px = (gx + 1.f) * (Wf * 0.5f) - 0.5f;
        const float py = (gy + 1.f) * (Wf * 0.5f) - 0.5f;
        const float x0f = floorf(px), y0f = floorf(py);
        const int   x0 = (int)x0f,   y0 = (int)y0f;
        const int   x1 = x0 + 1,     y1 = y0 + 1;
        const float wx1 = px - x0f,  wy1 = py - y0f;

        // validity-masked weights + clamped indices (== reference clip+mask)
        const float vx0 = (x0 >= 0 && x0 < Wf) ? (1.f - wx1) : 0.f;
        const float vx1 = (x1 >= 0 && x1 < Wf) ? wx1 : 0.f;
        const float vy0 = (y0 >= 0 && y0 < Wf) ? (1.f - wy1) : 0.f;
        const float vy1 = (y1 >= 0 && y1 < Wf) ? wy1 : 0.f;
        const int xc0 = min(max(x0, 0), Wf - 1);
        const int xc1 = min(max(x1, 0), Wf - 1);
        const int yc0 = min(max(y0, 0), Wf - 1);
        const int yc1 = min(max(y1, 0), Wf - 1);

        const int r0 = c_lvl_off[f] + yc0 * Wf;
        const int r1 = c_lvl_off[f] + yc1 * Wf;

        const float w00 = wf * vy0 * vx0;
        const float w01 = wf * vy0 * vx1;
        const float w10 = wf * vy1 * vx0;
        const float w11 = wf * vy1 * vx1;

        const float2 v00 = vbase[(r0 + xc0) * 256];
        const float2 v01 = vbase[(r0 + xc1) * 256];
        const float2 v10 = vbase[(r1 + xc0) * 256];
        const float2 v11 = vbase[(r1 + xc1) * 256];

        accx = fmaf(w00, v00.x, accx); accy = fmaf(w00, v00.y, accy);
        accx = fmaf(w01, v01.x, accx); accy = fmaf(w01, v01.y, accy);
        accx = fmaf(w10, v10.x, accx); accy = fmaf(w10, v10.y, accy);
        accx = fmaf(w11, v11.x, accx); accy = fmaf(w11, v11.y, accy);
    }

    const size_t ob = ((size_t)n * SPAD + q) * CCH + m * 64 + 2 * lane;
    __nv_bfloat16 h0 = __float2bfloat16(accx);
    __nv_bfloat16 h1 = __float2bfloat16(accy);
    *(__nv_bfloat162*)(g_smp_hi + ob) = __nv_bfloat162(h0, h1);
    *(__nv_bfloat162*)(g_smp_lo + ob) = __nv_bfloat162(
        __float2bfloat16(accx - __bfloat162float(h0)),
        __float2bfloat16(accy - __bfloat162float(h1)));
}

// ---------------------------------------------------------------------------
extern "C" void kernel_launch(void* const* d_in, const int* in_sizes, int n_in,
                              void* d_out, int out_size)
{
    const float* x            = (const float*)d_in[0];
    const float* pos          = (const float*)d_in[1];
    const float* valid_sizes  = (const float*)d_in[3];
    const float* valid_scales = (const float*)d_in[4];
    const float* Wv           = (const float*)d_in[5];
    const float* bv           = (const float*)d_in[6];
    const float* Wloc         = (const float*)d_in[7];
    const float* bloc         = (const float*)d_in[8];
    const float* Ww           = (const float*)d_in[9];
    const float* bw           = (const float*)d_in[10];
    const float* Wo           = (const float*)d_in[11];
    const float* bo           = (const float*)d_in[12];
    const float* scale        = (const float*)d_in[13];
    float* out = (float*)d_out;

    static bool attr_set = false;
    if (!attr_set) {
        cudaFuncSetAttribute(k_mma1, cudaFuncAttributeMaxDynamicSharedMemorySize, SMEM_SZ);
        cudaFuncSetAttribute(k_mma2, cudaFuncAttributeMaxDynamicSharedMemorySize, SMEM_SZ);
        attr_set = true;
    }

    dim3 gt(SPAD / 32, CCH / 32, NB);
    k_transpose<<<gt, 256>>>(x, pos);

    k_wconv<<<(CCH * CCH) / 256, 256>>>(Wv, Wo, Wloc, Ww, bloc, bw);

    dim3 g1(SPAD / 128, 5, NB);
    k_mma1<<<g1, 256, SMEM_SZ>>>(bv);

    const int nwarps = NB * SSQ * MM;
    k_sample<<<(nwarps * 32 + 255) / 256, 256>>>(valid_sizes, valid_scales);

    dim3 g2(SPAD / 128, CCH / 128, NB);
    k_mma2<<<g2, 256, SMEM_SZ>>>(bo, scale, out);
}